// round 12
// baseline (speedup 1.0000x reference)
#include <cuda_runtime.h>
#include <cuda_bf16.h>
#include <cuda_fp16.h>
#include <math.h>
#include <cstdint>

// Problem constants
#define NN   20000
#define NE   320000
#define DIN  50
#define K1   64
#define HID  1024
#define F3   726
#define NCLS 121
#define K2   2048
#define NOUT 128
#define SCAN_B 1000

// ---------------- scratch (device globals) -------------------------------------
__device__ __align__(128) __half g_A2[(size_t)NN * K2];   // [g1 | h1] fp16
__device__ __align__(128) __half g_A3[(size_t)NN * K2];   // [g2 | h2] fp16
__device__ __align__(128) __half g_B2[(size_t)HID * K2];  // [W2;S2]^T fp16
__device__ __align__(128) __half g_BO[(size_t)NOUT * K2]; // [W3m;S3m]^T fp16
__device__ __align__(128) __half g_W1T[(size_t)HID * K1];
__device__ __align__(128) __half g_g0h[(size_t)NN * K1];
__device__ int   g_deg[NN];
__device__ int   g_cursor[NN];
__device__ int   g_offs[NN + 1];
__device__ int   g_src[NE];
__device__ float g_w[NE];
__device__ int   g_bsum[32];

// ================= PTX helpers =================================================
__device__ __forceinline__ uint32_t smem_u32(const void* p) {
    uint32_t a;
    asm("{ .reg .u64 t; cvta.to.shared.u64 t, %1; cvt.u32.u64 %0, t; }" : "=r"(a) : "l"(p));
    return a;
}
__device__ __forceinline__ void cp16(uint32_t dst, const void* src) {
    uint64_t g = __cvta_generic_to_global(src);
    asm volatile("cp.async.cg.shared.global [%0], [%1], 16;" :: "r"(dst), "l"(g));
}
__device__ __forceinline__ void cp_commit() { asm volatile("cp.async.commit_group;" ::: "memory"); }
template <int N> __device__ __forceinline__ void cp_wait() {
    asm volatile("cp.async.wait_group %0;" :: "n"(N) : "memory");
}
__device__ __forceinline__ void ldm_x4(uint32_t* r, uint32_t addr) {
    asm volatile("ldmatrix.sync.aligned.m8n8.x4.shared.b16 {%0,%1,%2,%3}, [%4];"
                 : "=r"(r[0]), "=r"(r[1]), "=r"(r[2]), "=r"(r[3]) : "r"(addr));
}
__device__ __forceinline__ void mma16816h(float* c, const uint32_t* a, const uint32_t* b) {
    asm volatile(
        "mma.sync.aligned.m16n8k16.row.col.f32.f16.f16.f32 "
        "{%0,%1,%2,%3}, {%4,%5,%6,%7}, {%8,%9}, {%0,%1,%2,%3};"
        : "+f"(c[0]), "+f"(c[1]), "+f"(c[2]), "+f"(c[3])
        : "r"(a[0]), "r"(a[1]), "r"(a[2]), "r"(a[3]), "r"(b[0]), "r"(b[1]));
}

__device__ __forceinline__ float elu_f(float x) {
    return x > 0.f ? x : (expf(x) - 1.f);
}

// ---------------- prep: BO weights + W1 transpose + zero deg/cursor -------------
__global__ void prep_kernel(const float* __restrict__ W3, const float* __restrict__ S3,
                            const float* __restrict__ W1,
                            __half* __restrict__ BO, __half* __restrict__ W1T,
                            int* __restrict__ deg, int* __restrict__ cur) {
    int i = blockIdx.x * blockDim.x + threadIdx.x;
    int stride = gridDim.x * blockDim.x;
    if (i < NN) { deg[i] = 0; cur[i] = 0; }
    for (int j = i; j < NOUT * K2; j += stride) {
        int n = j >> 11, k = j & (K2 - 1);
        float v = 0.f;
        if (n < NCLS) {
            const float* Wp = (k < HID) ? (W3 + (size_t)k * F3) : (S3 + (size_t)(k - HID) * F3);
            #pragma unroll
            for (int hh = 0; hh < 6; hh++) v += Wp[hh * NCLS + n];
            v *= (1.0f / 6.0f);
        }
        BO[j] = __float2half(v);
    }
    for (int j = i; j < HID * K1; j += stride) {
        int n = j >> 6, k = j & (K1 - 1);
        float v = (k < DIN) ? W1[(size_t)k * HID + n] : 0.f;
        W1T[j] = __float2half(v);
    }
}

// ---------------- tiled transpose: W2/S2 [1024,1024] fp32 -> B2 [n][2048] fp16 ---
__global__ void transpose_w_kernel(const float* __restrict__ W2, const float* __restrict__ S2,
                                   __half* __restrict__ B2) {
    __shared__ float tile[32][33];
    const float* W = (blockIdx.z == 0) ? W2 : S2;
    int koff = blockIdx.z * HID;
    int k0 = blockIdx.x * 32;
    int n0 = blockIdx.y * 32;
    int tx = threadIdx.x, ty = threadIdx.y;
    #pragma unroll
    for (int r = 0; r < 4; r++) {
        int k = k0 + ty + r * 8;
        tile[ty + r * 8][tx] = W[(size_t)k * HID + n0 + tx];
    }
    __syncthreads();
    #pragma unroll
    for (int r = 0; r < 4; r++) {
        int n = n0 + ty + r * 8;
        B2[(size_t)n * K2 + koff + k0 + tx] = __float2half(tile[tx][ty + r * 8]);
    }
}

// ---------------- CSR build ------------------------------------------------------
__global__ void count_deg_kernel(const int* __restrict__ col, int* __restrict__ deg) {
    for (int e = blockIdx.x * blockDim.x + threadIdx.x; e < NE; e += gridDim.x * blockDim.x)
        atomicAdd(&deg[col[e]], 1);
}

__global__ void scanA_kernel(const int* __restrict__ counts, int* __restrict__ bsum) {
    __shared__ int ws[32];
    int b = blockIdx.x, tid = threadIdx.x;
    int wid = tid >> 5, lane = tid & 31;
    int i = b * SCAN_B + tid;
    int v = (tid < SCAN_B) ? counts[i] : 0;
    #pragma unroll
    for (int o = 16; o > 0; o >>= 1) v += __shfl_down_sync(0xFFFFFFFF, v, o);
    if (lane == 0) ws[wid] = v;
    __syncthreads();
    if (wid == 0) {
        int s = ws[lane];
        #pragma unroll
        for (int o = 16; o > 0; o >>= 1) s += __shfl_down_sync(0xFFFFFFFF, s, o);
        if (lane == 0) bsum[b] = s;
    }
}

__global__ void scanB_kernel(const int* __restrict__ counts, const int* __restrict__ bsum,
                             int* __restrict__ offs) {
    __shared__ int wsum[32];
    int b = blockIdx.x, tid = threadIdx.x;
    int wid = tid >> 5, lane = tid & 31;
    int pre = 0;
    for (int q = 0; q < b; q++) pre += bsum[q];
    int i = b * SCAN_B + tid;
    int v = (tid < SCAN_B) ? counts[i] : 0;
    int x = v;
    #pragma unroll
    for (int o = 1; o < 32; o <<= 1) {
        int y = __shfl_up_sync(0xFFFFFFFF, x, o);
        if (lane >= o) x += y;
    }
    if (lane == 31) wsum[wid] = x;
    __syncthreads();
    if (wid == 0) {
        int s = wsum[lane];
        #pragma unroll
        for (int o = 1; o < 32; o <<= 1) {
            int y = __shfl_up_sync(0xFFFFFFFF, s, o);
            if (lane >= o) s += y;
        }
        wsum[lane] = s;
    }
    __syncthreads();
    int inc = x + (wid > 0 ? wsum[wid - 1] : 0);
    if (tid < SCAN_B) offs[i] = pre + inc - v;
    if (b == gridDim.x - 1 && tid == SCAN_B - 1) offs[NN] = pre + inc;
}

__global__ void fill_csr_kernel(const int* __restrict__ row, const int* __restrict__ col,
                                const int* __restrict__ offs, int* __restrict__ cursor,
                                const int* __restrict__ deg,
                                int* __restrict__ csr_src, float* __restrict__ csr_w) {
    for (int e = blockIdx.x * blockDim.x + threadIdx.x; e < NE; e += gridDim.x * blockDim.x) {
        int r = row[e], c = col[e];
        int p = atomicAdd(&cursor[c], 1);
        int slot = offs[c] + p;
        int dr = deg[r];
        float nr = (dr > 0) ? rsqrtf((float)dr) : 0.0f;
        float nc = rsqrtf((float)deg[c]);
        csr_src[slot] = r;
        csr_w[slot] = nr * nc;
    }
}

// ---------------- g0 = agg(X), 50 features -> fp16 padded to 64 ------------------
__global__ void agg0_kernel(const float* __restrict__ X, __half* __restrict__ g0h,
                            const int* __restrict__ offs, const int* __restrict__ csr_src,
                            const float* __restrict__ csr_w) {
    int node = blockIdx.x;
    int t = threadIdx.x;
    float a0 = 0.f, a1 = 0.f;
    if (t < DIN) {
        int beg = offs[node], end = offs[node + 1];
        int j = beg;
        for (; j + 1 < end; j += 2) {
            int s0 = csr_src[j], s1 = csr_src[j + 1];
            float w0 = csr_w[j], w1 = csr_w[j + 1];
            a0 = fmaf(w0, __ldg(X + (size_t)s0 * DIN + t), a0);
            a1 = fmaf(w1, __ldg(X + (size_t)s1 * DIN + t), a1);
        }
        if (j < end)
            a0 = fmaf(csr_w[j], __ldg(X + (size_t)csr_src[j] * DIN + t), a0);
    }
    g0h[(size_t)node * K1 + t] = __float2half(t < DIN ? (a0 + a1) : 0.f);
}

// ---------------- layer-1 mma GEMM: h1 = elu(g0h @ W1T^T) -> A2 h-part -----------
#define RS1   144
#define ARR1  (128 * RS1)
#define G1_SMEM (2 * ARR1)

__global__ void __launch_bounds__(256, 2) mma_gemm1_kernel(
    const __half* __restrict__ A0, const __half* __restrict__ B0,
    __half* __restrict__ O, int M) {
    extern __shared__ char smem[];
    uint32_t sb = smem_u32(smem);
    int tid = threadIdx.x;
    int wid = tid >> 5, lane = tid & 31;
    int wm = wid >> 2, wn = wid & 3;
    int m0 = blockIdx.y * 128;
    int n0 = blockIdx.x * 128;

    int rrow = tid >> 1;
    int half = tid & 1;
    if (m0 + 128 > M) {
        int r = tid >> 1;
        if (m0 + r >= M) {
            uint32_t a = sb + r * RS1 + half * 64;
            #pragma unroll
            for (int q = 0; q < 4; q++)
                asm volatile("st.shared.v4.b32 [%0], {%1, %1, %1, %1};"
                             :: "r"(a + q * 16), "r"(0u) : "memory");
        }
    }
    if (m0 + rrow < M) {
        const __half* gp = A0 + (size_t)(m0 + rrow) * K1 + half * 32;
        uint32_t sa = sb + rrow * RS1 + half * 64;
        #pragma unroll
        for (int q = 0; q < 4; q++) cp16(sa + q * 16, gp + q * 8);
    }
    {
        const __half* gp = B0 + (size_t)(n0 + rrow) * K1 + half * 32;
        uint32_t sa = sb + ARR1 + rrow * RS1 + half * 64;
        #pragma unroll
        for (int q = 0; q < 4; q++) cp16(sa + q * 16, gp + q * 8);
    }
    cp_commit();
    cp_wait<0>();
    __syncthreads();

    float acc[4][4][4];
    #pragma unroll
    for (int i = 0; i < 4; i++)
        #pragma unroll
        for (int j = 0; j < 4; j++)
            #pragma unroll
            for (int q = 0; q < 4; q++) acc[i][j][q] = 0.f;

    int la = lane & 15, lha = (lane >> 4) & 1;
    int lbr = (lane & 7) + ((lane >> 4) & 1) * 8;
    int lbh = (lane >> 3) & 1;

    uint32_t aB = sb + (wm * 64) * RS1;
    uint32_t bB = sb + ARR1 + (wn * 32) * RS1;

    #pragma unroll
    for (int kk = 0; kk < 4; kk++) {
        uint32_t bh[4][2];
        #pragma unroll
        for (int pair = 0; pair < 2; pair++) {
            uint32_t bd = bB + (pair * 16 + lbr) * RS1 + lbh * 16 + kk * 32;
            uint32_t r4[4];
            ldm_x4(r4, bd);
            bh[pair * 2][0] = r4[0]; bh[pair * 2][1] = r4[1];
            bh[pair * 2 + 1][0] = r4[2]; bh[pair * 2 + 1][1] = r4[3];
        }
        #pragma unroll
        for (int im = 0; im < 4; im++) {
            uint32_t ah[4];
            uint32_t ad = aB + (im * 16 + la) * RS1 + lha * 16 + kk * 32;
            ldm_x4(ah, ad);
            #pragma unroll
            for (int in = 0; in < 4; in++)
                mma16816h(acc[im][in], ah, bh[in]);
        }
    }

    int cm = m0 + wm * 64 + (lane >> 2);
    int cn0 = n0 + wn * 32 + (lane & 3) * 2;
    #pragma unroll
    for (int im = 0; im < 4; im++) {
        #pragma unroll
        for (int hf = 0; hf < 2; hf++) {
            int r = cm + im * 16 + hf * 8;
            if (r >= M) continue;
            #pragma unroll
            for (int in = 0; in < 4; in++) {
                int c = cn0 + in * 8;
                __half2 hp = __floats2half2_rn(elu_f(acc[im][in][hf * 2 + 0]),
                                               elu_f(acc[im][in][hf * 2 + 1]));
                *(__half2*)(O + (size_t)r * K2 + HID + c) = hp;
            }
        }
    }
}

// ---------------- agg: g = agg(A[:,1024:]) -> A[:,0:1024], fp16, unroll 2 --------
__global__ void agg_half_kernel(__half* __restrict__ A,
                                const int* __restrict__ offs, const int* __restrict__ csr_src,
                                const float* __restrict__ csr_w) {
    int node = blockIdx.x;
    int tid = threadIdx.x;
    size_t cofs = HID + (size_t)tid * 4;
    float a0[4] = {0.f, 0.f, 0.f, 0.f};
    float a1[4] = {0.f, 0.f, 0.f, 0.f};
    int beg = offs[node], end = offs[node + 1];
    int j = beg;
    for (; j + 1 < end; j += 2) {
        int s0 = csr_src[j], s1 = csr_src[j + 1];
        float w0 = csr_w[j], w1 = csr_w[j + 1];
        uint2 p0 = __ldg((const uint2*)(A + (size_t)s0 * K2 + cofs));
        uint2 p1 = __ldg((const uint2*)(A + (size_t)s1 * K2 + cofs));
        float2 v00 = __half22float2(*(__half2*)&p0.x);
        float2 v01 = __half22float2(*(__half2*)&p0.y);
        float2 v10 = __half22float2(*(__half2*)&p1.x);
        float2 v11 = __half22float2(*(__half2*)&p1.y);
        a0[0] = fmaf(w0, v00.x, a0[0]); a0[1] = fmaf(w0, v00.y, a0[1]);
        a0[2] = fmaf(w0, v01.x, a0[2]); a0[3] = fmaf(w0, v01.y, a0[3]);
        a1[0] = fmaf(w1, v10.x, a1[0]); a1[1] = fmaf(w1, v10.y, a1[1]);
        a1[2] = fmaf(w1, v11.x, a1[2]); a1[3] = fmaf(w1, v11.y, a1[3]);
    }
    if (j < end) {
        int s0 = csr_src[j];
        float w0 = csr_w[j];
        uint2 p0 = __ldg((const uint2*)(A + (size_t)s0 * K2 + cofs));
        float2 v00 = __half22float2(*(__half2*)&p0.x);
        float2 v01 = __half22float2(*(__half2*)&p0.y);
        a0[0] = fmaf(w0, v00.x, a0[0]); a0[1] = fmaf(w0, v00.y, a0[1]);
        a0[2] = fmaf(w0, v01.x, a0[2]); a0[3] = fmaf(w0, v01.y, a0[3]);
    }
    __half2 o01 = __floats2half2_rn(a0[0] + a1[0], a0[1] + a1[1]);
    __half2 o23 = __floats2half2_rn(a0[2] + a1[2], a0[3] + a1[3]);
    uint2 pk;
    pk.x = *(uint32_t*)&o01;
    pk.y = *(uint32_t*)&o23;
    *(uint2*)(A + (size_t)node * K2 + (size_t)tid * 4) = pk;
}

// ---------------- gemm2: 512 threads, CTA tile 128(M)x256(N), KC=64 --------------
// Halves A L2 re-reads vs the 128x128 tile (8 n-tiles instead of 16).
#define KC    64
#define NCH   (K2 / KC)         // 32 chunks
#define RS    144
#define ARR_A (128 * RS)        // 18432
#define ARR_Bb (256 * RS)       // 36864
#define STG2  (ARR_A + ARR_Bb)  // 55296
#define G2_SMEM (2 * STG2)      // 110592 -> 1 CTA/SM, 16 warps

__device__ __forceinline__ void g2_load_chunk(
    uint32_t st, int k0,
    const __half* __restrict__ A, const __half* __restrict__ B,
    int tid, int m0, int n0, int M) {
    // A: 128 rows x 128B; row = tid>>2, 32B per thread (2 cp16)
    {
        int row = tid >> 2;
        int grow = m0 + row;
        if (grow < M) {
            const __half* gp = A + (size_t)grow * K2 + k0 + (tid & 3) * 16;
            uint32_t sa = st + row * RS + (tid & 3) * 32;
            cp16(sa, gp);
            cp16(sa + 16, gp + 8);
        }
    }
    // B: 256 rows x 128B; row = tid>>1, 64B per thread (4 cp16)
    {
        int row = tid >> 1;
        const __half* gp = B + (size_t)(n0 + row) * K2 + k0 + (tid & 1) * 32;
        uint32_t sa = st + ARR_A + row * RS + (tid & 1) * 64;
        #pragma unroll
        for (int q = 0; q < 4; q++) cp16(sa + q * 16, gp + q * 8);
    }
    cp_commit();
}

__global__ void __launch_bounds__(512, 1) mma_gemm2_kernel(
    const __half* __restrict__ Ain, const __half* __restrict__ Bin,
    __half* __restrict__ O, int M) {
    extern __shared__ char smem[];
    uint32_t sb = smem_u32(smem);
    int tid = threadIdx.x;
    int wid = tid >> 5, lane = tid & 31;
    int wm = wid >> 3, wn = wid & 7;     // 2m x 8n warps
    int m0 = blockIdx.y * 128;
    int n0 = blockIdx.x * 256;

    // zero-fill invalid A rows (edge m-tiles), both stages
    if (m0 + 128 > M) {
        int row = tid >> 2;
        if (m0 + row >= M) {
            #pragma unroll
            for (int s = 0; s < 2; s++) {
                uint32_t a = sb + s * STG2 + row * RS + (tid & 3) * 32;
                asm volatile("st.shared.v4.b32 [%0], {%1, %1, %1, %1};"
                             :: "r"(a), "r"(0u) : "memory");
                asm volatile("st.shared.v4.b32 [%0], {%1, %1, %1, %1};"
                             :: "r"(a + 16), "r"(0u) : "memory");
            }
        }
        __syncthreads();
    }

    float acc[4][4][4];
    #pragma unroll
    for (int i = 0; i < 4; i++)
        #pragma unroll
        for (int j = 0; j < 4; j++)
            #pragma unroll
            for (int q = 0; q < 4; q++) acc[i][j][q] = 0.f;

    g2_load_chunk(sb, 0, Ain, Bin, tid, m0, n0, M);

    int la = lane & 15, lha = (lane >> 4) & 1;
    int lbr = (lane & 7) + ((lane >> 4) & 1) * 8;
    int lbh = (lane >> 3) & 1;

    for (int i = 0; i < NCH; i++) {
        int b = i & 1;
        if (i + 1 < NCH) {
            g2_load_chunk(sb + (b ^ 1) * STG2, (i + 1) * KC, Ain, Bin, tid, m0, n0, M);
            cp_wait<1>();
        } else {
            cp_wait<0>();
        }
        __syncthreads();

        uint32_t st = sb + b * STG2;
        uint32_t aB = st + (wm * 64) * RS;
        uint32_t bB = st + ARR_A + (wn * 32) * RS;

        #pragma unroll
        for (int kk = 0; kk < 4; kk++) {
            uint32_t bh[4][2];
            #pragma unroll
            for (int pair = 0; pair < 2; pair++) {
                uint32_t bd = bB + (pair * 16 + lbr) * RS + lbh * 16 + kk * 32;
                uint32_t r4[4];
                ldm_x4(r4, bd);
                bh[pair * 2][0] = r4[0]; bh[pair * 2][1] = r4[1];
                bh[pair * 2 + 1][0] = r4[2]; bh[pair * 2 + 1][1] = r4[3];
            }
            #pragma unroll
            for (int im = 0; im < 4; im++) {
                uint32_t ah[4];
                uint32_t ad = aB + (im * 16 + la) * RS + lha * 16 + kk * 32;
                ldm_x4(ah, ad);
                #pragma unroll
                for (int in = 0; in < 4; in++)
                    mma16816h(acc[im][in], ah, bh[in]);
            }
        }
        __syncthreads();
    }

    int cm = m0 + wm * 64 + (lane >> 2);
    int cn0 = n0 + wn * 32 + (lane & 3) * 2;
    #pragma unroll
    for (int im = 0; im < 4; im++) {
        #pragma unroll
        for (int hf = 0; hf < 2; hf++) {
            int r = cm + im * 16 + hf * 8;
            if (r >= M) continue;
            #pragma unroll
            for (int in = 0; in < 4; in++) {
                int c = cn0 + in * 8;
                __half2 hp = __floats2half2_rn(elu_f(acc[im][in][hf * 2 + 0]),
                                               elu_f(acc[im][in][hf * 2 + 1]));
                *(__half2*)(O + (size_t)r * K2 + HID + c) = hp;
            }
        }
    }
}

// ---------------- gemm3: 256 threads, tile 128x128, KC=64, fp32 out --------------
#define STG_B (2 * ARR_A)
#define MMA_SMEM (2 * STG_B)    // 73728

__device__ __forceinline__ void mma_load_chunk(
    uint32_t st, int k0,
    const __half* __restrict__ A, const __half* __restrict__ B,
    int tid, int m0, int n0, int M) {
    int rrow = tid >> 1;
    int half = tid & 1;
    {
        int grow = m0 + rrow;
        if (grow < M) {
            const __half* gp = A + (size_t)grow * K2 + k0 + half * 32;
            uint32_t sa = st + rrow * RS + half * 64;
            #pragma unroll
            for (int q = 0; q < 4; q++) cp16(sa + q * 16, gp + q * 8);
        }
    }
    {
        const __half* gp = B + (size_t)(n0 + rrow) * K2 + k0 + half * 32;
        uint32_t sa = st + ARR_A + rrow * RS + half * 64;
        #pragma unroll
        for (int q = 0; q < 4; q++) cp16(sa + q * 16, gp + q * 8);
    }
    cp_commit();
}

__global__ void __launch_bounds__(256, 2) mma_gemm3_kernel(
    const __half* __restrict__ Ain, const __half* __restrict__ Bin,
    float* __restrict__ Out, int M) {
    extern __shared__ char smem[];
    uint32_t sb = smem_u32(smem);
    int tid = threadIdx.x;
    int wid = tid >> 5, lane = tid & 31;
    int wm = wid >> 2, wn = wid & 3;
    int m0 = blockIdx.y * 128;
    int n0 = blockIdx.x * 128;

    if (m0 + 128 > M) {
        for (int e = tid; e < 256; e += 256) {
            int s = e >> 7, r = e & 127;
            if (m0 + r >= M) {
                uint32_t a = sb + s * STG_B + r * RS;
                #pragma unroll
                for (int q = 0; q < 8; q++)
                    asm volatile("st.shared.v4.b32 [%0], {%1, %1, %1, %1};"
                                 :: "r"(a + q * 16), "r"(0u) : "memory");
            }
        }
        __syncthreads();
    }

    float acc[4][4][4];
    #pragma unroll
    for (int i = 0; i < 4; i++)
        #pragma unroll
        for (int j = 0; j < 4; j++)
            #pragma unroll
            for (int q = 0; q < 4; q++) acc[i][j][q] = 0.f;

    mma_load_chunk(sb, 0, Ain, Bin, tid, m0, n0, M);

    int la = lane & 15, lha = (lane >> 4) & 1;
    int lbr = (lane & 7) + ((lane >> 4) & 1) * 8;
    int lbh = (lane >> 3) & 1;

    for (int i = 0; i < NCH; i++) {
        int b = i & 1;
        if (i + 1 < NCH) {
            mma_load_chunk(sb + (b ^ 1) * STG_B, (i + 1) * KC, Ain, Bin, tid, m0, n0, M);
            cp_wait<1>();
        } else {
            cp_wait<0>();
        }
        __syncthreads();

        uint32_t st = sb + b * STG_B;
        uint32_t aB = st + (wm * 64) * RS;
        uint32_t bB = st + ARR_A + (wn * 32) * RS;

        #pragma unroll
        for (int kk = 0; kk < 4; kk++) {
            uint32_t bh[4][2];
            #pragma unroll
            for (int pair = 0; pair < 2; pair++) {
                uint32_t bd = bB + (pair * 16 + lbr) * RS + lbh * 16 + kk * 32;
                uint32_t r4[4];
                ldm_x4(r4, bd);
                bh[pair * 2][0] = r4[0]; bh[pair * 2][1] = r4[1];
                bh[pair * 2 + 1][0] = r4[2]; bh[pair * 2 + 1][1] = r4[3];
            }
            #pragma unroll
            for (int im = 0; im < 4; im++) {
                uint32_t ah[4];
                uint32_t ad = aB + (im * 16 + la) * RS + lha * 16 + kk * 32;
                ldm_x4(ah, ad);
                #pragma unroll
                for (int in = 0; in < 4; in++)
                    mma16816h(acc[im][in], ah, bh[in]);
            }
        }
        __syncthreads();
    }

    int cm = m0 + wm * 64 + (lane >> 2);
    int cn0 = n0 + wn * 32 + (lane & 3) * 2;
    #pragma unroll
    for (int im = 0; im < 4; im++) {
        #pragma unroll
        for (int hf = 0; hf < 2; hf++) {
            int r = cm + im * 16 + hf * 8;
            if (r >= M) continue;
            #pragma unroll
            for (int in = 0; in < 4; in++) {
                int c = cn0 + in * 8;
                float v0 = acc[im][in][hf * 2 + 0];
                float v1 = acc[im][in][hf * 2 + 1];
                if (c < NCLS)     Out[(size_t)r * NCLS + c] = v0;
                if (c + 1 < NCLS) Out[(size_t)r * NCLS + c + 1] = v1;
            }
        }
    }
}

// ---------------- launcher -------------------------------------------------------
extern "C" void kernel_launch(void* const* d_in, const int* in_sizes, int n_in,
                              void* d_out, int out_size) {
    const float* X  = (const float*)d_in[0];
    const int*   ei = (const int*)d_in[1];
    const float* W1 = (const float*)d_in[2];
    const float* W2 = (const float*)d_in[3];
    const float* S2 = (const float*)d_in[4];
    const float* W3 = (const float*)d_in[5];
    const float* S3 = (const float*)d_in[6];
    float* out = (float*)d_out;

    const int* row = ei;
    const int* col = ei + NE;

    float* w;
    int *deg, *cur, *offs, *src, *bsum;
    __half *A2, *A3, *B2, *BO, *W1T, *g0h;
    cudaGetSymbolAddress((void**)&deg,  g_deg);
    cudaGetSymbolAddress((void**)&cur,  g_cursor);
    cudaGetSymbolAddress((void**)&offs, g_offs);
    cudaGetSymbolAddress((void**)&src,  g_src);
    cudaGetSymbolAddress((void**)&w,    g_w);
    cudaGetSymbolAddress((void**)&bsum, g_bsum);
    cudaGetSymbolAddress((void**)&A2,   g_A2);
    cudaGetSymbolAddress((void**)&A3,   g_A3);
    cudaGetSymbolAddress((void**)&B2,   g_B2);
    cudaGetSymbolAddress((void**)&BO,   g_BO);
    cudaGetSymbolAddress((void**)&W1T,  g_W1T);
    cudaGetSymbolAddress((void**)&g0h,  g_g0h);

    cudaFuncSetAttribute(mma_gemm2_kernel, cudaFuncAttributeMaxDynamicSharedMemorySize, G2_SMEM);
    cudaFuncSetAttribute(mma_gemm3_kernel, cudaFuncAttributeMaxDynamicSharedMemorySize, MMA_SMEM);
    cudaFuncSetAttribute(mma_gemm1_kernel, cudaFuncAttributeMaxDynamicSharedMemorySize, G1_SMEM);

    // 0-1: weight prep
    prep_kernel<<<1024, 256>>>(W3, S3, W1, BO, W1T, deg, cur);
    {
        dim3 grid(32, 32, 2);
        dim3 blk(32, 8);
        transpose_w_kernel<<<grid, blk>>>(W2, S2, B2);
    }
    // 2-5: CSR build
    count_deg_kernel<<<512, 256>>>(col, deg);
    scanA_kernel<<<NN / SCAN_B, 1024>>>(deg, bsum);
    scanB_kernel<<<NN / SCAN_B, 1024>>>(deg, bsum, offs);
    fill_csr_kernel<<<512, 256>>>(row, col, offs, cur, deg, src, w);

    // 6: g0 = agg(X) -> fp16 padded [N,64]
    agg0_kernel<<<NN, 64>>>(X, g0h, offs, src, w);

    // 7: h1 = elu(g0h @ W1T^T) -> A2[:,1024:] fp16
    {
        dim3 grid(HID / 128, (NN + 127) / 128);
        mma_gemm1_kernel<<<grid, 256, G1_SMEM>>>(g0h, W1T, A2, NN);
    }

    // 8: g1 = agg(h1) -> A2[:, 0:1024]
    agg_half_kernel<<<NN, 256>>>(A2, offs, src, w);

    // 9: h2 = elu([g1,h1] @ [W2;S2]) -> A3[:,1024:] fp16  (wide 128x256 tiles)
    {
        dim3 grid(K2 / 256, (NN + 127) / 128);
        mma_gemm2_kernel<<<grid, 512, G2_SMEM>>>(A2, B2, A3, NN);
    }

    // 10: g2 = agg(h2) -> A3[:, 0:1024]
    agg_half_kernel<<<NN, 256>>>(A3, offs, src, w);

    // 11: out = [g2,h2] @ [W3m;S3m] -> d_out
    {
        dim3 grid(1, (NN + 127) / 128);
        mma_gemm3_kernel<<<grid, 256, MMA_SMEM>>>(A3, BO, out, NN);
    }
}

// round 13
// speedup vs baseline: 1.5036x; 1.5036x over previous
#include <cuda_runtime.h>
#include <cuda_bf16.h>
#include <cuda_fp16.h>
#include <math.h>
#include <cstdint>

// Problem constants
#define NN   20000
#define NE   320000
#define DIN  50
#define K1   64          // padded K for layer-1 mma (50 -> 64)
#define HID  1024
#define F3   726
#define NCLS 121
#define K2   2048        // concatenated K for layers 2/3
#define NOUT 128         // padded output width of last GEMM (121 -> 128)
#define SCAN_B 1000      // elements per scan block (20 blocks * 1000 = 20000)

// ---------------- scratch (device globals) -------------------------------------
__device__ __align__(128) __half g_A2[(size_t)NN * K2];   // [g1 | h1] fp16
__device__ __align__(128) __half g_A3[(size_t)NN * K2];   // [g2 | h2] fp16
__device__ __align__(128) __half g_B2[(size_t)HID * K2];  // [W2;S2]^T fp16
__device__ __align__(128) __half g_BO[(size_t)NOUT * K2]; // [W3m;S3m]^T fp16
__device__ __align__(128) __half g_W1T[(size_t)HID * K1]; // W1^T fp16 (padded K)
__device__ __align__(128) __half g_g0h[(size_t)NN * K1];  // agg(X) fp16 (padded K)
__device__ int   g_deg[NN];
__device__ int   g_cursor[NN];
__device__ int   g_offs[NN + 1];
__device__ int   g_src[NE];
__device__ float g_w[NE];
__device__ int   g_bsum[32];

// ================= PTX helpers =================================================
__device__ __forceinline__ uint32_t smem_u32(const void* p) {
    uint32_t a;
    asm("{ .reg .u64 t; cvta.to.shared.u64 t, %1; cvt.u32.u64 %0, t; }" : "=r"(a) : "l"(p));
    return a;
}
__device__ __forceinline__ void cp16(uint32_t dst, const void* src) {
    uint64_t g = __cvta_generic_to_global(src);
    asm volatile("cp.async.cg.shared.global [%0], [%1], 16;" :: "r"(dst), "l"(g));
}
__device__ __forceinline__ void cp_commit() { asm volatile("cp.async.commit_group;" ::: "memory"); }
template <int N> __device__ __forceinline__ void cp_wait() {
    asm volatile("cp.async.wait_group %0;" :: "n"(N) : "memory");
}
__device__ __forceinline__ void ldm_x4(uint32_t* r, uint32_t addr) {
    asm volatile("ldmatrix.sync.aligned.m8n8.x4.shared.b16 {%0,%1,%2,%3}, [%4];"
                 : "=r"(r[0]), "=r"(r[1]), "=r"(r[2]), "=r"(r[3]) : "r"(addr));
}
__device__ __forceinline__ void mma16816h(float* c, const uint32_t* a, const uint32_t* b) {
    asm volatile(
        "mma.sync.aligned.m16n8k16.row.col.f32.f16.f16.f32 "
        "{%0,%1,%2,%3}, {%4,%5,%6,%7}, {%8,%9}, {%0,%1,%2,%3};"
        : "+f"(c[0]), "+f"(c[1]), "+f"(c[2]), "+f"(c[3])
        : "r"(a[0]), "r"(a[1]), "r"(a[2]), "r"(a[3]), "r"(b[0]), "r"(b[1]));
}

__device__ __forceinline__ float elu_f(float x) {
    return x > 0.f ? x : (expf(x) - 1.f);
}

// ---------------- prep: BO weights + W1 transpose + zero deg/cursor -------------
__global__ void prep_kernel(const float* __restrict__ W3, const float* __restrict__ S3,
                            const float* __restrict__ W1,
                            __half* __restrict__ BO, __half* __restrict__ W1T,
                            int* __restrict__ deg, int* __restrict__ cur) {
    int i = blockIdx.x * blockDim.x + threadIdx.x;
    int stride = gridDim.x * blockDim.x;
    if (i < NN) { deg[i] = 0; cur[i] = 0; }
    for (int j = i; j < NOUT * K2; j += stride) {
        int n = j >> 11, k = j & (K2 - 1);
        float v = 0.f;
        if (n < NCLS) {
            const float* Wp = (k < HID) ? (W3 + (size_t)k * F3) : (S3 + (size_t)(k - HID) * F3);
            #pragma unroll
            for (int hh = 0; hh < 6; hh++) v += Wp[hh * NCLS + n];
            v *= (1.0f / 6.0f);
        }
        BO[j] = __float2half(v);
    }
    for (int j = i; j < HID * K1; j += stride) {
        int n = j >> 6, k = j & (K1 - 1);
        float v = (k < DIN) ? W1[(size_t)k * HID + n] : 0.f;
        W1T[j] = __float2half(v);
    }
}

// ---------------- tiled transpose: W2/S2 [1024,1024] fp32 -> B2 [n][2048] fp16 ---
__global__ void transpose_w_kernel(const float* __restrict__ W2, const float* __restrict__ S2,
                                   __half* __restrict__ B2) {
    __shared__ float tile[32][33];
    const float* W = (blockIdx.z == 0) ? W2 : S2;
    int koff = blockIdx.z * HID;
    int k0 = blockIdx.x * 32;
    int n0 = blockIdx.y * 32;
    int tx = threadIdx.x, ty = threadIdx.y;
    #pragma unroll
    for (int r = 0; r < 4; r++) {
        int k = k0 + ty + r * 8;
        tile[ty + r * 8][tx] = W[(size_t)k * HID + n0 + tx];
    }
    __syncthreads();
    #pragma unroll
    for (int r = 0; r < 4; r++) {
        int n = n0 + ty + r * 8;
        B2[(size_t)n * K2 + koff + k0 + tx] = __float2half(tile[tx][ty + r * 8]);
    }
}

// ---------------- CSR build ------------------------------------------------------
__global__ void count_deg_kernel(const int* __restrict__ col, int* __restrict__ deg) {
    for (int e = blockIdx.x * blockDim.x + threadIdx.x; e < NE; e += gridDim.x * blockDim.x)
        atomicAdd(&deg[col[e]], 1);
}

__global__ void scanA_kernel(const int* __restrict__ counts, int* __restrict__ bsum) {
    __shared__ int ws[32];
    int b = blockIdx.x, tid = threadIdx.x;
    int wid = tid >> 5, lane = tid & 31;
    int i = b * SCAN_B + tid;
    int v = (tid < SCAN_B) ? counts[i] : 0;
    #pragma unroll
    for (int o = 16; o > 0; o >>= 1) v += __shfl_down_sync(0xFFFFFFFF, v, o);
    if (lane == 0) ws[wid] = v;
    __syncthreads();
    if (wid == 0) {
        int s = ws[lane];
        #pragma unroll
        for (int o = 16; o > 0; o >>= 1) s += __shfl_down_sync(0xFFFFFFFF, s, o);
        if (lane == 0) bsum[b] = s;
    }
}

__global__ void scanB_kernel(const int* __restrict__ counts, const int* __restrict__ bsum,
                             int* __restrict__ offs) {
    __shared__ int wsum[32];
    int b = blockIdx.x, tid = threadIdx.x;
    int wid = tid >> 5, lane = tid & 31;
    int pre = 0;
    for (int q = 0; q < b; q++) pre += bsum[q];
    int i = b * SCAN_B + tid;
    int v = (tid < SCAN_B) ? counts[i] : 0;
    int x = v;
    #pragma unroll
    for (int o = 1; o < 32; o <<= 1) {
        int y = __shfl_up_sync(0xFFFFFFFF, x, o);
        if (lane >= o) x += y;
    }
    if (lane == 31) wsum[wid] = x;
    __syncthreads();
    if (wid == 0) {
        int s = wsum[lane];
        #pragma unroll
        for (int o = 1; o < 32; o <<= 1) {
            int y = __shfl_up_sync(0xFFFFFFFF, s, o);
            if (lane >= o) s += y;
        }
        wsum[lane] = s;
    }
    __syncthreads();
    int inc = x + (wid > 0 ? wsum[wid - 1] : 0);
    if (tid < SCAN_B) offs[i] = pre + inc - v;
    if (b == gridDim.x - 1 && tid == SCAN_B - 1) offs[NN] = pre + inc;
}

__global__ void fill_csr_kernel(const int* __restrict__ row, const int* __restrict__ col,
                                const int* __restrict__ offs, int* __restrict__ cursor,
                                const int* __restrict__ deg,
                                int* __restrict__ csr_src, float* __restrict__ csr_w) {
    for (int e = blockIdx.x * blockDim.x + threadIdx.x; e < NE; e += gridDim.x * blockDim.x) {
        int r = row[e], c = col[e];
        int p = atomicAdd(&cursor[c], 1);
        int slot = offs[c] + p;
        int dr = deg[r];
        float nr = (dr > 0) ? rsqrtf((float)dr) : 0.0f;
        float nc = rsqrtf((float)deg[c]);
        csr_src[slot] = r;
        csr_w[slot] = nr * nc;
    }
}

// ---------------- g0 = agg(X), 50 features -> fp16 padded to 64 ------------------
__global__ void agg0_kernel(const float* __restrict__ X, __half* __restrict__ g0h,
                            const int* __restrict__ offs, const int* __restrict__ csr_src,
                            const float* __restrict__ csr_w) {
    int node = blockIdx.x;
    int t = threadIdx.x;   // 64 threads
    float a0 = 0.f, a1 = 0.f;
    if (t < DIN) {
        int beg = offs[node], end = offs[node + 1];
        int j = beg;
        for (; j + 1 < end; j += 2) {
            int s0 = csr_src[j], s1 = csr_src[j + 1];
            float w0 = csr_w[j], w1 = csr_w[j + 1];
            a0 = fmaf(w0, __ldg(X + (size_t)s0 * DIN + t), a0);
            a1 = fmaf(w1, __ldg(X + (size_t)s1 * DIN + t), a1);
        }
        if (j < end)
            a0 = fmaf(csr_w[j], __ldg(X + (size_t)csr_src[j] * DIN + t), a0);
    }
    g0h[(size_t)node * K1 + t] = __float2half(t < DIN ? (a0 + a1) : 0.f);
}

// ---------------- layer-1 mma GEMM: h1 = elu(g0h @ W1T^T) -> A2 h-part -----------
// K=64, single chunk, tile 128x128, 8 warps (2x4).
#define RS1   144
#define ARR1  (128 * RS1)        // 18432
#define G1_SMEM (2 * ARR1)       // 36864

__global__ void __launch_bounds__(256, 2) mma_gemm1_kernel(
    const __half* __restrict__ A0, const __half* __restrict__ B0,
    __half* __restrict__ O, int M) {
    extern __shared__ char smem[];
    uint32_t sb = smem_u32(smem);
    int tid = threadIdx.x;
    int wid = tid >> 5, lane = tid & 31;
    int wm = wid >> 2, wn = wid & 3;
    int m0 = blockIdx.y * 128;
    int n0 = blockIdx.x * 128;

    int rrow = tid >> 1;
    int half = tid & 1;
    // zero-fill invalid A rows first
    if (m0 + 128 > M) {
        int r = tid >> 1;
        if (m0 + r >= M) {
            uint32_t a = sb + r * RS1 + half * 64;
            #pragma unroll
            for (int q = 0; q < 4; q++)
                asm volatile("st.shared.v4.b32 [%0], {%1, %1, %1, %1};"
                             :: "r"(a + q * 16), "r"(0u) : "memory");
        }
    }
    // A: 128 rows x 128 B (64 fp16)
    if (m0 + rrow < M) {
        const __half* gp = A0 + (size_t)(m0 + rrow) * K1 + half * 32;
        uint32_t sa = sb + rrow * RS1 + half * 64;
        #pragma unroll
        for (int q = 0; q < 4; q++) cp16(sa + q * 16, gp + q * 8);
    }
    // B: 128 rows (always valid, n0+127 < 1024)
    {
        const __half* gp = B0 + (size_t)(n0 + rrow) * K1 + half * 32;
        uint32_t sa = sb + ARR1 + rrow * RS1 + half * 64;
        #pragma unroll
        for (int q = 0; q < 4; q++) cp16(sa + q * 16, gp + q * 8);
    }
    cp_commit();
    cp_wait<0>();
    __syncthreads();

    float acc[4][4][4];
    #pragma unroll
    for (int i = 0; i < 4; i++)
        #pragma unroll
        for (int j = 0; j < 4; j++)
            #pragma unroll
            for (int q = 0; q < 4; q++) acc[i][j][q] = 0.f;

    int la = lane & 15, lha = (lane >> 4) & 1;
    int lbr = (lane & 7) + ((lane >> 4) & 1) * 8;
    int lbh = (lane >> 3) & 1;

    uint32_t aB = sb + (wm * 64) * RS1;
    uint32_t bB = sb + ARR1 + (wn * 32) * RS1;

    #pragma unroll
    for (int kk = 0; kk < 4; kk++) {
        uint32_t bh[4][2];
        #pragma unroll
        for (int pair = 0; pair < 2; pair++) {
            uint32_t bd = bB + (pair * 16 + lbr) * RS1 + lbh * 16 + kk * 32;
            uint32_t r4[4];
            ldm_x4(r4, bd);
            bh[pair * 2][0] = r4[0]; bh[pair * 2][1] = r4[1];
            bh[pair * 2 + 1][0] = r4[2]; bh[pair * 2 + 1][1] = r4[3];
        }
        #pragma unroll
        for (int im = 0; im < 4; im++) {
            uint32_t ah[4];
            uint32_t ad = aB + (im * 16 + la) * RS1 + lha * 16 + kk * 32;
            ldm_x4(ah, ad);
            #pragma unroll
            for (int in = 0; in < 4; in++)
                mma16816h(acc[im][in], ah, bh[in]);
        }
    }

    int cm = m0 + wm * 64 + (lane >> 2);
    int cn0 = n0 + wn * 32 + (lane & 3) * 2;
    #pragma unroll
    for (int im = 0; im < 4; im++) {
        #pragma unroll
        for (int hf = 0; hf < 2; hf++) {
            int r = cm + im * 16 + hf * 8;
            if (r >= M) continue;
            #pragma unroll
            for (int in = 0; in < 4; in++) {
                int c = cn0 + in * 8;
                __half2 hp = __floats2half2_rn(elu_f(acc[im][in][hf * 2 + 0]),
                                               elu_f(acc[im][in][hf * 2 + 1]));
                *(__half2*)(O + (size_t)r * K2 + HID + c) = hp;
            }
        }
    }
}

// ---------------- agg: g = agg(A[:,1024:]) -> A[:,0:1024], fp16, unroll 2 --------
__global__ void agg_half_kernel(__half* __restrict__ A,
                                const int* __restrict__ offs, const int* __restrict__ csr_src,
                                const float* __restrict__ csr_w) {
    int node = blockIdx.x;
    int tid = threadIdx.x;
    size_t cofs = HID + (size_t)tid * 4;
    float a0[4] = {0.f, 0.f, 0.f, 0.f};
    float a1[4] = {0.f, 0.f, 0.f, 0.f};
    int beg = offs[node], end = offs[node + 1];
    int j = beg;
    for (; j + 1 < end; j += 2) {
        int s0 = csr_src[j], s1 = csr_src[j + 1];
        float w0 = csr_w[j], w1 = csr_w[j + 1];
        uint2 p0 = __ldg((const uint2*)(A + (size_t)s0 * K2 + cofs));
        uint2 p1 = __ldg((const uint2*)(A + (size_t)s1 * K2 + cofs));
        float2 v00 = __half22float2(*(__half2*)&p0.x);
        float2 v01 = __half22float2(*(__half2*)&p0.y);
        float2 v10 = __half22float2(*(__half2*)&p1.x);
        float2 v11 = __half22float2(*(__half2*)&p1.y);
        a0[0] = fmaf(w0, v00.x, a0[0]); a0[1] = fmaf(w0, v00.y, a0[1]);
        a0[2] = fmaf(w0, v01.x, a0[2]); a0[3] = fmaf(w0, v01.y, a0[3]);
        a1[0] = fmaf(w1, v10.x, a1[0]); a1[1] = fmaf(w1, v10.y, a1[1]);
        a1[2] = fmaf(w1, v11.x, a1[2]); a1[3] = fmaf(w1, v11.y, a1[3]);
    }
    if (j < end) {
        int s0 = csr_src[j];
        float w0 = csr_w[j];
        uint2 p0 = __ldg((const uint2*)(A + (size_t)s0 * K2 + cofs));
        float2 v00 = __half22float2(*(__half2*)&p0.x);
        float2 v01 = __half22float2(*(__half2*)&p0.y);
        a0[0] = fmaf(w0, v00.x, a0[0]); a0[1] = fmaf(w0, v00.y, a0[1]);
        a0[2] = fmaf(w0, v01.x, a0[2]); a0[3] = fmaf(w0, v01.y, a0[3]);
    }
    __half2 o01 = __floats2half2_rn(a0[0] + a1[0], a0[1] + a1[1]);
    __half2 o23 = __floats2half2_rn(a0[2] + a1[2], a0[3] + a1[3]);
    uint2 pk;
    pk.x = *(uint32_t*)&o01;
    pk.y = *(uint32_t*)&o23;
    *(uint2*)(A + (size_t)node * K2 + (size_t)tid * 4) = pk;
}

// ---------------- fp16 mma.sync GEMM (K=2048, KC=64, 2 CTAs/SM) ------------------
#define KC    64
#define NCH   (K2 / KC)         // 32 chunks
#define RS    144
#define ARR_B (128 * RS)
#define STG_B (2 * ARR_B)
#define MMA_SMEM (2 * STG_B)    // 73728

__device__ __forceinline__ void mma_load_chunk(
    uint32_t st, int k0,
    const __half* __restrict__ A, const __half* __restrict__ B,
    int tid, int m0, int n0, int M) {
    int rrow = tid >> 1;
    int half = tid & 1;
    {
        int grow = m0 + rrow;
        if (grow < M) {
            const __half* gp = A + (size_t)grow * K2 + k0 + half * 32;
            uint32_t sa = st + rrow * RS + half * 64;
            #pragma unroll
            for (int q = 0; q < 4; q++) cp16(sa + q * 16, gp + q * 8);
        }
    }
    {
        const __half* gp = B + (size_t)(n0 + rrow) * K2 + k0 + half * 32;
        uint32_t sa = st + ARR_B + rrow * RS + half * 64;
        #pragma unroll
        for (int q = 0; q < 4; q++) cp16(sa + q * 16, gp + q * 8);
    }
    cp_commit();
}

template <int MODE>
__global__ void __launch_bounds__(256, 2) mma_gemm_kernel(
    const __half* __restrict__ Ain, const __half* __restrict__ Bin,
    __half* __restrict__ O, float* __restrict__ Out, int M) {
    extern __shared__ char smem[];
    uint32_t sb = smem_u32(smem);
    int tid = threadIdx.x;
    int wid = tid >> 5, lane = tid & 31;
    int wm = wid >> 2, wn = wid & 3;
    int m0 = blockIdx.y * 128;
    int n0 = blockIdx.x * 128;

    if (m0 + 128 > M) {
        for (int e = tid; e < 256; e += 256) {
            int s = e >> 7, r = e & 127;
            if (m0 + r >= M) {
                uint32_t a = sb + s * STG_B + r * RS;
                #pragma unroll
                for (int q = 0; q < 8; q++)
                    asm volatile("st.shared.v4.b32 [%0], {%1, %1, %1, %1};"
                                 :: "r"(a + q * 16), "r"(0u) : "memory");
            }
        }
        __syncthreads();
    }

    float acc[4][4][4];
    #pragma unroll
    for (int i = 0; i < 4; i++)
        #pragma unroll
        for (int j = 0; j < 4; j++)
            #pragma unroll
            for (int q = 0; q < 4; q++) acc[i][j][q] = 0.f;

    mma_load_chunk(sb, 0, Ain, Bin, tid, m0, n0, M);

    int la = lane & 15, lha = (lane >> 4) & 1;
    int lbr = (lane & 7) + ((lane >> 4) & 1) * 8;
    int lbh = (lane >> 3) & 1;

    for (int i = 0; i < NCH; i++) {
        int b = i & 1;
        if (i + 1 < NCH) {
            mma_load_chunk(sb + (b ^ 1) * STG_B, (i + 1) * KC, Ain, Bin, tid, m0, n0, M);
            cp_wait<1>();
        } else {
            cp_wait<0>();
        }
        __syncthreads();

        uint32_t st = sb + b * STG_B;
        uint32_t aB = st + (wm * 64) * RS;
        uint32_t bB = st + ARR_B + (wn * 32) * RS;

        #pragma unroll
        for (int kk = 0; kk < 4; kk++) {
            uint32_t bh[4][2];
            #pragma unroll
            for (int pair = 0; pair < 2; pair++) {
                uint32_t bd = bB + (pair * 16 + lbr) * RS + lbh * 16 + kk * 32;
                uint32_t r4[4];
                ldm_x4(r4, bd);
                bh[pair * 2][0] = r4[0]; bh[pair * 2][1] = r4[1];
                bh[pair * 2 + 1][0] = r4[2]; bh[pair * 2 + 1][1] = r4[3];
            }
            #pragma unroll
            for (int im = 0; im < 4; im++) {
                uint32_t ah[4];
                uint32_t ad = aB + (im * 16 + la) * RS + lha * 16 + kk * 32;
                ldm_x4(ah, ad);
                #pragma unroll
                for (int in = 0; in < 4; in++)
                    mma16816h(acc[im][in], ah, bh[in]);
            }
        }
        __syncthreads();
    }

    int cm = m0 + wm * 64 + (lane >> 2);
    int cn0 = n0 + wn * 32 + (lane & 3) * 2;
    #pragma unroll
    for (int im = 0; im < 4; im++) {
        #pragma unroll
        for (int hf = 0; hf < 2; hf++) {
            int r = cm + im * 16 + hf * 8;
            if (r >= M) continue;
            #pragma unroll
            for (int in = 0; in < 4; in++) {
                int c = cn0 + in * 8;
                float v0 = acc[im][in][hf * 2 + 0];
                float v1 = acc[im][in][hf * 2 + 1];
                if (MODE == 0) {
                    __half2 hp = __floats2half2_rn(elu_f(v0), elu_f(v1));
                    *(__half2*)(O + (size_t)r * K2 + HID + c) = hp;
                } else {
                    if (c < NCLS)     Out[(size_t)r * NCLS + c] = v0;
                    if (c + 1 < NCLS) Out[(size_t)r * NCLS + c + 1] = v1;
                }
            }
        }
    }
}

// ---------------- launcher -------------------------------------------------------
extern "C" void kernel_launch(void* const* d_in, const int* in_sizes, int n_in,
                              void* d_out, int out_size) {
    const float* X  = (const float*)d_in[0];
    const int*   ei = (const int*)d_in[1];
    const float* W1 = (const float*)d_in[2];
    const float* W2 = (const float*)d_in[3];
    const float* S2 = (const float*)d_in[4];
    const float* W3 = (const float*)d_in[5];
    const float* S3 = (const float*)d_in[6];
    float* out = (float*)d_out;

    const int* row = ei;
    const int* col = ei + NE;

    float* w;
    int *deg, *cur, *offs, *src, *bsum;
    __half *A2, *A3, *B2, *BO, *W1T, *g0h;
    cudaGetSymbolAddress((void**)&deg,  g_deg);
    cudaGetSymbolAddress((void**)&cur,  g_cursor);
    cudaGetSymbolAddress((void**)&offs, g_offs);
    cudaGetSymbolAddress((void**)&src,  g_src);
    cudaGetSymbolAddress((void**)&w,    g_w);
    cudaGetSymbolAddress((void**)&bsum, g_bsum);
    cudaGetSymbolAddress((void**)&A2,   g_A2);
    cudaGetSymbolAddress((void**)&A3,   g_A3);
    cudaGetSymbolAddress((void**)&B2,   g_B2);
    cudaGetSymbolAddress((void**)&BO,   g_BO);
    cudaGetSymbolAddress((void**)&W1T,  g_W1T);
    cudaGetSymbolAddress((void**)&g0h,  g_g0h);

    cudaFuncSetAttribute(mma_gemm_kernel<0>, cudaFuncAttributeMaxDynamicSharedMemorySize, MMA_SMEM);
    cudaFuncSetAttribute(mma_gemm_kernel<1>, cudaFuncAttributeMaxDynamicSharedMemorySize, MMA_SMEM);
    cudaFuncSetAttribute(mma_gemm1_kernel, cudaFuncAttributeMaxDynamicSharedMemorySize, G1_SMEM);

    // 0-1: weight prep (BO + W1T + deg/cur zero; coalesced B2 transpose)
    prep_kernel<<<1024, 256>>>(W3, S3, W1, BO, W1T, deg, cur);
    {
        dim3 grid(32, 32, 2);
        dim3 blk(32, 8);
        transpose_w_kernel<<<grid, blk>>>(W2, S2, B2);
    }
    // 2-5: CSR build (two-level scan)
    count_deg_kernel<<<512, 256>>>(col, deg);
    scanA_kernel<<<NN / SCAN_B, 1024>>>(deg, bsum);
    scanB_kernel<<<NN / SCAN_B, 1024>>>(deg, bsum, offs);
    fill_csr_kernel<<<512, 256>>>(row, col, offs, cur, deg, src, w);

    // 6: g0 = agg(X) -> fp16 padded [N,64]
    agg0_kernel<<<NN, 64>>>(X, g0h, offs, src, w);

    // 7: h1 = elu(g0h @ W1T^T) -> A2[:,1024:] fp16 (tensor cores)
    {
        dim3 grid(HID / 128, (NN + 127) / 128);
        mma_gemm1_kernel<<<grid, 256, G1_SMEM>>>(g0h, W1T, A2, NN);
    }

    // 8: g1 = agg(h1) -> A2[:, 0:1024]
    agg_half_kernel<<<NN, 256>>>(A2, offs, src, w);

    // 9: h2 = elu([g1,h1] @ [W2;S2]) -> A3[:,1024:] fp16
    {
        dim3 grid(HID / 128, (NN + 127) / 128);
        mma_gemm_kernel<0><<<grid, 256, MMA_SMEM>>>(A2, B2, A3, nullptr, NN);
    }

    // 10: g2 = agg(h2) -> A3[:, 0:1024]
    agg_half_kernel<<<NN, 256>>>(A3, offs, src, w);

    // 11: out = [g2,h2] @ [W3m;S3m] -> d_out
    {
        dim3 grid(1, (NN + 127) / 128);
        mma_gemm_kernel<1><<<grid, 256, MMA_SMEM>>>(A3, BO, nullptr, out, NN);
    }
}

// round 14
// speedup vs baseline: 1.5044x; 1.0006x over previous
#include <cuda_runtime.h>
#include <cuda_bf16.h>
#include <cuda_fp16.h>
#include <math.h>
#include <cstdint>

// Problem constants
#define NN   20000
#define NE   320000
#define DIN  50
#define K1   64          // padded K for layer-1 mma (50 -> 64)
#define HID  1024
#define F3   726
#define NCLS 121
#define K2   2048        // concatenated K for layers 2/3
#define NOUT 128         // padded output width of last GEMM (121 -> 128)
#define SCAN_B 1000

// ---------------- scratch (device globals) -------------------------------------
__device__ __align__(128) __half g_A2[(size_t)NN * K2];   // [g1 | h1] fp16
__device__ __align__(128) __half g_A3[(size_t)NN * K2];   // [g2 | h2] fp16
__device__ __align__(128) __half g_B2[(size_t)HID * K2];  // [W2;S2]^T fp16
__device__ __align__(128) __half g_BO[(size_t)NOUT * K2]; // [W3m;S3m]^T fp16
__device__ __align__(128) __half g_W1T[(size_t)HID * K1];
__device__ __align__(128) __half g_g0h[(size_t)NN * K1];
__device__ int   g_deg[NN];
__device__ int   g_cursor[NN];
__device__ int   g_offs[NN + 1];
__device__ int   g_src[NE];
__device__ float g_w[NE];
__device__ int   g_bsum[32];

// ================= PTX helpers =================================================
__device__ __forceinline__ uint32_t smem_u32(const void* p) {
    uint32_t a;
    asm("{ .reg .u64 t; cvta.to.shared.u64 t, %1; cvt.u32.u64 %0, t; }" : "=r"(a) : "l"(p));
    return a;
}
__device__ __forceinline__ void cp16(uint32_t dst, const void* src) {
    uint64_t g = __cvta_generic_to_global(src);
    asm volatile("cp.async.cg.shared.global [%0], [%1], 16;" :: "r"(dst), "l"(g));
}
__device__ __forceinline__ void cp_commit() { asm volatile("cp.async.commit_group;" ::: "memory"); }
template <int N> __device__ __forceinline__ void cp_wait() {
    asm volatile("cp.async.wait_group %0;" :: "n"(N) : "memory");
}
__device__ __forceinline__ void ldm_x4(uint32_t* r, uint32_t addr) {
    asm volatile("ldmatrix.sync.aligned.m8n8.x4.shared.b16 {%0,%1,%2,%3}, [%4];"
                 : "=r"(r[0]), "=r"(r[1]), "=r"(r[2]), "=r"(r[3]) : "r"(addr));
}
__device__ __forceinline__ void mma16816h(float* c, const uint32_t* a, const uint32_t* b) {
    asm volatile(
        "mma.sync.aligned.m16n8k16.row.col.f32.f16.f16.f32 "
        "{%0,%1,%2,%3}, {%4,%5,%6,%7}, {%8,%9}, {%0,%1,%2,%3};"
        : "+f"(c[0]), "+f"(c[1]), "+f"(c[2]), "+f"(c[3])
        : "r"(a[0]), "r"(a[1]), "r"(a[2]), "r"(a[3]), "r"(b[0]), "r"(b[1]));
}

__device__ __forceinline__ float elu_f(float x) {
    return x > 0.f ? x : (expf(x) - 1.f);
}

// ---------------- prep: BO weights + W1 transpose (no CSR state) -----------------
__global__ void prep_kernel(const float* __restrict__ W3, const float* __restrict__ S3,
                            const float* __restrict__ W1,
                            __half* __restrict__ BO, __half* __restrict__ W1T) {
    int i = blockIdx.x * blockDim.x + threadIdx.x;
    int stride = gridDim.x * blockDim.x;
    for (int j = i; j < NOUT * K2; j += stride) {
        int n = j >> 11, k = j & (K2 - 1);
        float v = 0.f;
        if (n < NCLS) {
            const float* Wp = (k < HID) ? (W3 + (size_t)k * F3) : (S3 + (size_t)(k - HID) * F3);
            #pragma unroll
            for (int hh = 0; hh < 6; hh++) v += Wp[hh * NCLS + n];
            v *= (1.0f / 6.0f);
        }
        BO[j] = __float2half(v);
    }
    for (int j = i; j < HID * K1; j += stride) {
        int n = j >> 6, k = j & (K1 - 1);
        float v = (k < DIN) ? W1[(size_t)k * HID + n] : 0.f;
        W1T[j] = __float2half(v);
    }
}

// ---------------- tiled transpose: W2/S2 [1024,1024] fp32 -> B2 [n][2048] fp16 ---
__global__ void transpose_w_kernel(const float* __restrict__ W2, const float* __restrict__ S2,
                                   __half* __restrict__ B2) {
    __shared__ float tile[32][33];
    const float* W = (blockIdx.z == 0) ? W2 : S2;
    int koff = blockIdx.z * HID;
    int k0 = blockIdx.x * 32;
    int n0 = blockIdx.y * 32;
    int tx = threadIdx.x, ty = threadIdx.y;
    #pragma unroll
    for (int r = 0; r < 4; r++) {
        int k = k0 + ty + r * 8;
        tile[ty + r * 8][tx] = W[(size_t)k * HID + n0 + tx];
    }
    __syncthreads();
    #pragma unroll
    for (int r = 0; r < 4; r++) {
        int n = n0 + ty + r * 8;
        B2[(size_t)n * K2 + koff + k0 + tx] = __float2half(tile[tx][ty + r * 8]);
    }
}

// ---------------- CSR build ------------------------------------------------------
__global__ void count_deg_kernel(const int* __restrict__ col, int* __restrict__ deg) {
    for (int e = blockIdx.x * blockDim.x + threadIdx.x; e < NE; e += gridDim.x * blockDim.x)
        atomicAdd(&deg[col[e]], 1);
}

__global__ void scanA_kernel(const int* __restrict__ counts, int* __restrict__ bsum) {
    __shared__ int ws[32];
    int b = blockIdx.x, tid = threadIdx.x;
    int wid = tid >> 5, lane = tid & 31;
    int i = b * SCAN_B + tid;
    int v = (tid < SCAN_B) ? counts[i] : 0;
    #pragma unroll
    for (int o = 16; o > 0; o >>= 1) v += __shfl_down_sync(0xFFFFFFFF, v, o);
    if (lane == 0) ws[wid] = v;
    __syncthreads();
    if (wid == 0) {
        int s = ws[lane];
        #pragma unroll
        for (int o = 16; o > 0; o >>= 1) s += __shfl_down_sync(0xFFFFFFFF, s, o);
        if (lane == 0) bsum[b] = s;
    }
}

__global__ void scanB_kernel(const int* __restrict__ counts, const int* __restrict__ bsum,
                             int* __restrict__ offs) {
    __shared__ int wsum[32];
    int b = blockIdx.x, tid = threadIdx.x;
    int wid = tid >> 5, lane = tid & 31;
    int pre = 0;
    for (int q = 0; q < b; q++) pre += bsum[q];
    int i = b * SCAN_B + tid;
    int v = (tid < SCAN_B) ? counts[i] : 0;
    int x = v;
    #pragma unroll
    for (int o = 1; o < 32; o <<= 1) {
        int y = __shfl_up_sync(0xFFFFFFFF, x, o);
        if (lane >= o) x += y;
    }
    if (lane == 31) wsum[wid] = x;
    __syncthreads();
    if (wid == 0) {
        int s = wsum[lane];
        #pragma unroll
        for (int o = 1; o < 32; o <<= 1) {
            int y = __shfl_up_sync(0xFFFFFFFF, s, o);
            if (lane >= o) s += y;
        }
        wsum[lane] = s;
    }
    __syncthreads();
    int inc = x + (wid > 0 ? wsum[wid - 1] : 0);
    if (tid < SCAN_B) offs[i] = pre + inc - v;
    if (b == gridDim.x - 1 && tid == SCAN_B - 1) offs[NN] = pre + inc;
}

__global__ void fill_csr_kernel(const int* __restrict__ row, const int* __restrict__ col,
                                const int* __restrict__ offs, int* __restrict__ cursor,
                                const int* __restrict__ deg,
                                int* __restrict__ csr_src, float* __restrict__ csr_w) {
    for (int e = blockIdx.x * blockDim.x + threadIdx.x; e < NE; e += gridDim.x * blockDim.x) {
        int r = row[e], c = col[e];
        int p = atomicAdd(&cursor[c], 1);
        int slot = offs[c] + p;
        int dr = deg[r];
        float nr = (dr > 0) ? rsqrtf((float)dr) : 0.0f;
        float nc = rsqrtf((float)deg[c]);
        csr_src[slot] = r;
        csr_w[slot] = nr * nc;
    }
}

// ---------------- g0 = agg(X), 50 features -> fp16 padded to 64 ------------------
__global__ void agg0_kernel(const float* __restrict__ X, __half* __restrict__ g0h,
                            const int* __restrict__ offs, const int* __restrict__ csr_src,
                            const float* __restrict__ csr_w) {
    int node = blockIdx.x;
    int t = threadIdx.x;
    float a0 = 0.f, a1 = 0.f;
    if (t < DIN) {
        int beg = offs[node], end = offs[node + 1];
        int j = beg;
        for (; j + 1 < end; j += 2) {
            int s0 = csr_src[j], s1 = csr_src[j + 1];
            float w0 = csr_w[j], w1 = csr_w[j + 1];
            a0 = fmaf(w0, __ldg(X + (size_t)s0 * DIN + t), a0);
            a1 = fmaf(w1, __ldg(X + (size_t)s1 * DIN + t), a1);
        }
        if (j < end)
            a0 = fmaf(csr_w[j], __ldg(X + (size_t)csr_src[j] * DIN + t), a0);
    }
    g0h[(size_t)node * K1 + t] = __float2half(t < DIN ? (a0 + a1) : 0.f);
}

// ---------------- layer-1 mma GEMM ------------------------------------------------
#define RS1   144
#define ARR1  (128 * RS1)
#define G1_SMEM (2 * ARR1)

__global__ void __launch_bounds__(256, 2) mma_gemm1_kernel(
    const __half* __restrict__ A0, const __half* __restrict__ B0,
    __half* __restrict__ O, int M) {
    extern __shared__ char smem[];
    uint32_t sb = smem_u32(smem);
    int tid = threadIdx.x;
    int wid = tid >> 5, lane = tid & 31;
    int wm = wid >> 2, wn = wid & 3;
    int m0 = blockIdx.y * 128;
    int n0 = blockIdx.x * 128;

    int rrow = tid >> 1;
    int half = tid & 1;
    if (m0 + 128 > M) {
        int r = tid >> 1;
        if (m0 + r >= M) {
            uint32_t a = sb + r * RS1 + half * 64;
            #pragma unroll
            for (int q = 0; q < 4; q++)
                asm volatile("st.shared.v4.b32 [%0], {%1, %1, %1, %1};"
                             :: "r"(a + q * 16), "r"(0u) : "memory");
        }
    }
    if (m0 + rrow < M) {
        const __half* gp = A0 + (size_t)(m0 + rrow) * K1 + half * 32;
        uint32_t sa = sb + rrow * RS1 + half * 64;
        #pragma unroll
        for (int q = 0; q < 4; q++) cp16(sa + q * 16, gp + q * 8);
    }
    {
        const __half* gp = B0 + (size_t)(n0 + rrow) * K1 + half * 32;
        uint32_t sa = sb + ARR1 + rrow * RS1 + half * 64;
        #pragma unroll
        for (int q = 0; q < 4; q++) cp16(sa + q * 16, gp + q * 8);
    }
    cp_commit();
    cp_wait<0>();
    __syncthreads();

    float acc[4][4][4];
    #pragma unroll
    for (int i = 0; i < 4; i++)
        #pragma unroll
        for (int j = 0; j < 4; j++)
            #pragma unroll
            for (int q = 0; q < 4; q++) acc[i][j][q] = 0.f;

    int la = lane & 15, lha = (lane >> 4) & 1;
    int lbr = (lane & 7) + ((lane >> 4) & 1) * 8;
    int lbh = (lane >> 3) & 1;

    uint32_t aB = sb + (wm * 64) * RS1;
    uint32_t bB = sb + ARR1 + (wn * 32) * RS1;

    #pragma unroll
    for (int kk = 0; kk < 4; kk++) {
        uint32_t bh[4][2];
        #pragma unroll
        for (int pair = 0; pair < 2; pair++) {
            uint32_t bd = bB + (pair * 16 + lbr) * RS1 + lbh * 16 + kk * 32;
            uint32_t r4[4];
            ldm_x4(r4, bd);
            bh[pair * 2][0] = r4[0]; bh[pair * 2][1] = r4[1];
            bh[pair * 2 + 1][0] = r4[2]; bh[pair * 2 + 1][1] = r4[3];
        }
        #pragma unroll
        for (int im = 0; im < 4; im++) {
            uint32_t ah[4];
            uint32_t ad = aB + (im * 16 + la) * RS1 + lha * 16 + kk * 32;
            ldm_x4(ah, ad);
            #pragma unroll
            for (int in = 0; in < 4; in++)
                mma16816h(acc[im][in], ah, bh[in]);
        }
    }

    int cm = m0 + wm * 64 + (lane >> 2);
    int cn0 = n0 + wn * 32 + (lane & 3) * 2;
    #pragma unroll
    for (int im = 0; im < 4; im++) {
        #pragma unroll
        for (int hf = 0; hf < 2; hf++) {
            int r = cm + im * 16 + hf * 8;
            if (r >= M) continue;
            #pragma unroll
            for (int in = 0; in < 4; in++) {
                int c = cn0 + in * 8;
                __half2 hp = __floats2half2_rn(elu_f(acc[im][in][hf * 2 + 0]),
                                               elu_f(acc[im][in][hf * 2 + 1]));
                *(__half2*)(O + (size_t)r * K2 + HID + c) = hp;
            }
        }
    }
}

// ---------------- agg: g = agg(A[:,1024:]) -> A[:,0:1024], fp16, unroll 2 --------
__global__ void agg_half_kernel(__half* __restrict__ A,
                                const int* __restrict__ offs, const int* __restrict__ csr_src,
                                const float* __restrict__ csr_w) {
    int node = blockIdx.x;
    int tid = threadIdx.x;
    size_t cofs = HID + (size_t)tid * 4;
    float a0[4] = {0.f, 0.f, 0.f, 0.f};
    float a1[4] = {0.f, 0.f, 0.f, 0.f};
    int beg = offs[node], end = offs[node + 1];
    int j = beg;
    for (; j + 1 < end; j += 2) {
        int s0 = csr_src[j], s1 = csr_src[j + 1];
        float w0 = csr_w[j], w1 = csr_w[j + 1];
        uint2 p0 = __ldg((const uint2*)(A + (size_t)s0 * K2 + cofs));
        uint2 p1 = __ldg((const uint2*)(A + (size_t)s1 * K2 + cofs));
        float2 v00 = __half22float2(*(__half2*)&p0.x);
        float2 v01 = __half22float2(*(__half2*)&p0.y);
        float2 v10 = __half22float2(*(__half2*)&p1.x);
        float2 v11 = __half22float2(*(__half2*)&p1.y);
        a0[0] = fmaf(w0, v00.x, a0[0]); a0[1] = fmaf(w0, v00.y, a0[1]);
        a0[2] = fmaf(w0, v01.x, a0[2]); a0[3] = fmaf(w0, v01.y, a0[3]);
        a1[0] = fmaf(w1, v10.x, a1[0]); a1[1] = fmaf(w1, v10.y, a1[1]);
        a1[2] = fmaf(w1, v11.x, a1[2]); a1[3] = fmaf(w1, v11.y, a1[3]);
    }
    if (j < end) {
        int s0 = csr_src[j];
        float w0 = csr_w[j];
        uint2 p0 = __ldg((const uint2*)(A + (size_t)s0 * K2 + cofs));
        float2 v00 = __half22float2(*(__half2*)&p0.x);
        float2 v01 = __half22float2(*(__half2*)&p0.y);
        a0[0] = fmaf(w0, v00.x, a0[0]); a0[1] = fmaf(w0, v00.y, a0[1]);
        a0[2] = fmaf(w0, v01.x, a0[2]); a0[3] = fmaf(w0, v01.y, a0[3]);
    }
    __half2 o01 = __floats2half2_rn(a0[0] + a1[0], a0[1] + a1[1]);
    __half2 o23 = __floats2half2_rn(a0[2] + a1[2], a0[3] + a1[3]);
    uint2 pk;
    pk.x = *(uint32_t*)&o01;
    pk.y = *(uint32_t*)&o23;
    *(uint2*)(A + (size_t)node * K2 + (size_t)tid * 4) = pk;
}

// ---------------- fp16 mma.sync GEMM (K=2048, KC=64, 2 CTAs/SM) ------------------
#define KC    64
#define NCH   (K2 / KC)
#define RS    144
#define ARR_B (128 * RS)
#define STG_B (2 * ARR_B)
#define MMA_SMEM (2 * STG_B)

__device__ __forceinline__ void mma_load_chunk(
    uint32_t st, int k0,
    const __half* __restrict__ A, const __half* __restrict__ B,
    int tid, int m0, int n0, int M) {
    int rrow = tid >> 1;
    int half = tid & 1;
    {
        int grow = m0 + rrow;
        if (grow < M) {
            const __half* gp = A + (size_t)grow * K2 + k0 + half * 32;
            uint32_t sa = st + rrow * RS + half * 64;
            #pragma unroll
            for (int q = 0; q < 4; q++) cp16(sa + q * 16, gp + q * 8);
        }
    }
    {
        const __half* gp = B + (size_t)(n0 + rrow) * K2 + k0 + half * 32;
        uint32_t sa = st + ARR_B + rrow * RS + half * 64;
        #pragma unroll
        for (int q = 0; q < 4; q++) cp16(sa + q * 16, gp + q * 8);
    }
    cp_commit();
}

template <int MODE>
__global__ void __launch_bounds__(256, 2) mma_gemm_kernel(
    const __half* __restrict__ Ain, const __half* __restrict__ Bin,
    __half* __restrict__ O, float* __restrict__ Out, int M) {
    extern __shared__ char smem[];
    uint32_t sb = smem_u32(smem);
    int tid = threadIdx.x;
    int wid = tid >> 5, lane = tid & 31;
    int wm = wid >> 2, wn = wid & 3;
    int m0 = blockIdx.y * 128;
    int n0 = blockIdx.x * 128;

    if (m0 + 128 > M) {
        for (int e = tid; e < 256; e += 256) {
            int s = e >> 7, r = e & 127;
            if (m0 + r >= M) {
                uint32_t a = sb + s * STG_B + r * RS;
                #pragma unroll
                for (int q = 0; q < 8; q++)
                    asm volatile("st.shared.v4.b32 [%0], {%1, %1, %1, %1};"
                                 :: "r"(a + q * 16), "r"(0u) : "memory");
            }
        }
        __syncthreads();
    }

    float acc[4][4][4];
    #pragma unroll
    for (int i = 0; i < 4; i++)
        #pragma unroll
        for (int j = 0; j < 4; j++)
            #pragma unroll
            for (int q = 0; q < 4; q++) acc[i][j][q] = 0.f;

    mma_load_chunk(sb, 0, Ain, Bin, tid, m0, n0, M);

    int la = lane & 15, lha = (lane >> 4) & 1;
    int lbr = (lane & 7) + ((lane >> 4) & 1) * 8;
    int lbh = (lane >> 3) & 1;

    for (int i = 0; i < NCH; i++) {
        int b = i & 1;
        if (i + 1 < NCH) {
            mma_load_chunk(sb + (b ^ 1) * STG_B, (i + 1) * KC, Ain, Bin, tid, m0, n0, M);
            cp_wait<1>();
        } else {
            cp_wait<0>();
        }
        __syncthreads();

        uint32_t st = sb + b * STG_B;
        uint32_t aB = st + (wm * 64) * RS;
        uint32_t bB = st + ARR_B + (wn * 32) * RS;

        #pragma unroll
        for (int kk = 0; kk < 4; kk++) {
            uint32_t bh[4][2];
            #pragma unroll
            for (int pair = 0; pair < 2; pair++) {
                uint32_t bd = bB + (pair * 16 + lbr) * RS + lbh * 16 + kk * 32;
                uint32_t r4[4];
                ldm_x4(r4, bd);
                bh[pair * 2][0] = r4[0]; bh[pair * 2][1] = r4[1];
                bh[pair * 2 + 1][0] = r4[2]; bh[pair * 2 + 1][1] = r4[3];
            }
            #pragma unroll
            for (int im = 0; im < 4; im++) {
                uint32_t ah[4];
                uint32_t ad = aB + (im * 16 + la) * RS + lha * 16 + kk * 32;
                ldm_x4(ah, ad);
                #pragma unroll
                for (int in = 0; in < 4; in++)
                    mma16816h(acc[im][in], ah, bh[in]);
            }
        }
        __syncthreads();
    }

    int cm = m0 + wm * 64 + (lane >> 2);
    int cn0 = n0 + wn * 32 + (lane & 3) * 2;
    #pragma unroll
    for (int im = 0; im < 4; im++) {
        #pragma unroll
        for (int hf = 0; hf < 2; hf++) {
            int r = cm + im * 16 + hf * 8;
            if (r >= M) continue;
            #pragma unroll
            for (int in = 0; in < 4; in++) {
                int c = cn0 + in * 8;
                float v0 = acc[im][in][hf * 2 + 0];
                float v1 = acc[im][in][hf * 2 + 1];
                if (MODE == 0) {
                    __half2 hp = __floats2half2_rn(elu_f(v0), elu_f(v1));
                    *(__half2*)(O + (size_t)r * K2 + HID + c) = hp;
                } else {
                    if (c < NCLS)     Out[(size_t)r * NCLS + c] = v0;
                    if (c + 1 < NCLS) Out[(size_t)r * NCLS + c + 1] = v1;
                }
            }
        }
    }
}

// ---------------- launcher -------------------------------------------------------
extern "C" void kernel_launch(void* const* d_in, const int* in_sizes, int n_in,
                              void* d_out, int out_size) {
    const float* X  = (const float*)d_in[0];
    const int*   ei = (const int*)d_in[1];
    const float* W1 = (const float*)d_in[2];
    const float* W2 = (const float*)d_in[3];
    const float* S2 = (const float*)d_in[4];
    const float* W3 = (const float*)d_in[5];
    const float* S3 = (const float*)d_in[6];
    float* out = (float*)d_out;

    const int* row = ei;
    const int* col = ei + NE;

    float* w;
    int *deg, *cur, *offs, *src, *bsum;
    __half *A2, *A3, *B2, *BO, *W1T, *g0h;
    cudaGetSymbolAddress((void**)&deg,  g_deg);
    cudaGetSymbolAddress((void**)&cur,  g_cursor);
    cudaGetSymbolAddress((void**)&offs, g_offs);
    cudaGetSymbolAddress((void**)&src,  g_src);
    cudaGetSymbolAddress((void**)&w,    g_w);
    cudaGetSymbolAddress((void**)&bsum, g_bsum);
    cudaGetSymbolAddress((void**)&A2,   g_A2);
    cudaGetSymbolAddress((void**)&A3,   g_A3);
    cudaGetSymbolAddress((void**)&B2,   g_B2);
    cudaGetSymbolAddress((void**)&BO,   g_BO);
    cudaGetSymbolAddress((void**)&W1T,  g_W1T);
    cudaGetSymbolAddress((void**)&g0h,  g_g0h);

    cudaFuncSetAttribute(mma_gemm_kernel<0>, cudaFuncAttributeMaxDynamicSharedMemorySize, MMA_SMEM);
    cudaFuncSetAttribute(mma_gemm_kernel<1>, cudaFuncAttributeMaxDynamicSharedMemorySize, MMA_SMEM);
    cudaFuncSetAttribute(mma_gemm1_kernel, cudaFuncAttributeMaxDynamicSharedMemorySize, G1_SMEM);

    // stream/event created once, on the (uncaptured) correctness call
    static cudaStream_t s2 = nullptr;
    static cudaEvent_t evFork = nullptr, evJoin = nullptr;
    if (s2 == nullptr) {
        cudaStreamCreateWithFlags(&s2, cudaStreamNonBlocking);
        cudaEventCreateWithFlags(&evFork, cudaEventDisableTiming);
        cudaEventCreateWithFlags(&evJoin, cudaEventDisableTiming);
    }

    // ---- fork: side stream does weight prep (BO, W1T, B2) ----
    cudaEventRecord(evFork, 0);
    cudaStreamWaitEvent(s2, evFork, 0);
    prep_kernel<<<1024, 256, 0, s2>>>(W3, S3, W1, BO, W1T);
    {
        dim3 grid(32, 32, 2);
        dim3 blk(32, 8);
        transpose_w_kernel<<<grid, blk, 0, s2>>>(W2, S2, B2);
    }
    cudaEventRecord(evJoin, s2);

    // ---- main stream: CSR build + agg0 (independent of weights) ----
    cudaMemsetAsync(deg, 0, NN * sizeof(int));
    cudaMemsetAsync(cur, 0, NN * sizeof(int));
    count_deg_kernel<<<512, 256>>>(col, deg);
    scanA_kernel<<<NN / SCAN_B, 1024>>>(deg, bsum);
    scanB_kernel<<<NN / SCAN_B, 1024>>>(deg, bsum, offs);
    fill_csr_kernel<<<512, 256>>>(row, col, offs, cur, deg, src, w);
    agg0_kernel<<<NN, 64>>>(X, g0h, offs, src, w);

    // ---- join: gemm1 needs W1T (side) + g0h (main) ----
    cudaStreamWaitEvent(0, evJoin, 0);

    // h1 = elu(g0h @ W1T^T) -> A2[:,1024:]
    {
        dim3 grid(HID / 128, (NN + 127) / 128);
        mma_gemm1_kernel<<<grid, 256, G1_SMEM>>>(g0h, W1T, A2, NN);
    }
    // g1 = agg(h1) -> A2[:, 0:1024]
    agg_half_kernel<<<NN, 256>>>(A2, offs, src, w);
    // h2 = elu([g1,h1] @ [W2;S2]) -> A3[:,1024:]
    {
        dim3 grid(HID / 128, (NN + 127) / 128);
        mma_gemm_kernel<0><<<grid, 256, MMA_SMEM>>>(A2, B2, A3, nullptr, NN);
    }
    // g2 = agg(h2) -> A3[:, 0:1024]
    agg_half_kernel<<<NN, 256>>>(A3, offs, src, w);
    // out = [g2,h2] @ [W3m;S3m] -> d_out
    {
        dim3 grid(1, (NN + 127) / 128);
        mma_gemm_kernel<1><<<grid, 256, MMA_SMEM>>>(A3, BO, nullptr, out, NN);
    }
}

// round 15
// speedup vs baseline: 1.5086x; 1.0028x over previous
#include <cuda_runtime.h>
#include <cuda_bf16.h>
#include <cuda_fp16.h>
#include <math.h>
#include <cstdint>

// Problem constants
#define NN   20000
#define NE   320000
#define DIN  50
#define K1   64
#define HID  1024
#define F3   726
#define NCLS 121
#define K2   2048
#define NOUT 128
#define SCAN_B 1000

// ---------------- scratch (device globals) -------------------------------------
__device__ __align__(128) __half g_A2[(size_t)NN * K2];   // [g1 | h1] fp16
__device__ __align__(128) __half g_A3[(size_t)NN * K2];   // [g2 | h2] fp16
__device__ __align__(128) __half g_B2[(size_t)HID * K2];  // [W2;S2]^T fp16
__device__ __align__(128) __half g_BO[(size_t)NOUT * K2]; // [W3m;S3m]^T fp16
__device__ __align__(128) __half g_W1T[(size_t)HID * K1];
__device__ __align__(128) __half g_g0h[(size_t)NN * K1];
__device__ __align__(128) float g_P[2 * (size_t)NN * NCLS]; // split-K partials
__device__ int   g_deg[NN];
__device__ int   g_cursor[NN];
__device__ int   g_offs[NN + 1];
__device__ int   g_src[NE];
__device__ float g_w[NE];
__device__ int   g_bsum[32];

// ================= PTX helpers =================================================
__device__ __forceinline__ uint32_t smem_u32(const void* p) {
    uint32_t a;
    asm("{ .reg .u64 t; cvta.to.shared.u64 t, %1; cvt.u32.u64 %0, t; }" : "=r"(a) : "l"(p));
    return a;
}
__device__ __forceinline__ void cp16(uint32_t dst, const void* src) {
    uint64_t g = __cvta_generic_to_global(src);
    asm volatile("cp.async.cg.shared.global [%0], [%1], 16;" :: "r"(dst), "l"(g));
}
__device__ __forceinline__ void cp_commit() { asm volatile("cp.async.commit_group;" ::: "memory"); }
template <int N> __device__ __forceinline__ void cp_wait() {
    asm volatile("cp.async.wait_group %0;" :: "n"(N) : "memory");
}
__device__ __forceinline__ void ldm_x4(uint32_t* r, uint32_t addr) {
    asm volatile("ldmatrix.sync.aligned.m8n8.x4.shared.b16 {%0,%1,%2,%3}, [%4];"
                 : "=r"(r[0]), "=r"(r[1]), "=r"(r[2]), "=r"(r[3]) : "r"(addr));
}
__device__ __forceinline__ void mma16816h(float* c, const uint32_t* a, const uint32_t* b) {
    asm volatile(
        "mma.sync.aligned.m16n8k16.row.col.f32.f16.f16.f32 "
        "{%0,%1,%2,%3}, {%4,%5,%6,%7}, {%8,%9}, {%0,%1,%2,%3};"
        : "+f"(c[0]), "+f"(c[1]), "+f"(c[2]), "+f"(c[3])
        : "r"(a[0]), "r"(a[1]), "r"(a[2]), "r"(a[3]), "r"(b[0]), "r"(b[1]));
}

__device__ __forceinline__ float elu_f(float x) {
    return x > 0.f ? x : (expf(x) - 1.f);
}

// ---------------- prep: BO weights + W1 transpose --------------------------------
__global__ void prep_kernel(const float* __restrict__ W3, const float* __restrict__ S3,
                            const float* __restrict__ W1,
                            __half* __restrict__ BO, __half* __restrict__ W1T) {
    int i = blockIdx.x * blockDim.x + threadIdx.x;
    int stride = gridDim.x * blockDim.x;
    for (int j = i; j < NOUT * K2; j += stride) {
        int n = j >> 11, k = j & (K2 - 1);
        float v = 0.f;
        if (n < NCLS) {
            const float* Wp = (k < HID) ? (W3 + (size_t)k * F3) : (S3 + (size_t)(k - HID) * F3);
            #pragma unroll
            for (int hh = 0; hh < 6; hh++) v += Wp[hh * NCLS + n];
            v *= (1.0f / 6.0f);
        }
        BO[j] = __float2half(v);
    }
    for (int j = i; j < HID * K1; j += stride) {
        int n = j >> 6, k = j & (K1 - 1);
        float v = (k < DIN) ? W1[(size_t)k * HID + n] : 0.f;
        W1T[j] = __float2half(v);
    }
}

// ---------------- tiled transpose: W2/S2 [1024,1024] fp32 -> B2 [n][2048] fp16 ---
__global__ void transpose_w_kernel(const float* __restrict__ W2, const float* __restrict__ S2,
                                   __half* __restrict__ B2) {
    __shared__ float tile[32][33];
    const float* W = (blockIdx.z == 0) ? W2 : S2;
    int koff = blockIdx.z * HID;
    int k0 = blockIdx.x * 32;
    int n0 = blockIdx.y * 32;
    int tx = threadIdx.x, ty = threadIdx.y;
    #pragma unroll
    for (int r = 0; r < 4; r++) {
        int k = k0 + ty + r * 8;
        tile[ty + r * 8][tx] = W[(size_t)k * HID + n0 + tx];
    }
    __syncthreads();
    #pragma unroll
    for (int r = 0; r < 4; r++) {
        int n = n0 + ty + r * 8;
        B2[(size_t)n * K2 + koff + k0 + tx] = __float2half(tile[tx][ty + r * 8]);
    }
}

// ---------------- CSR build ------------------------------------------------------
__global__ void count_deg_kernel(const int* __restrict__ col, int* __restrict__ deg) {
    for (int e = blockIdx.x * blockDim.x + threadIdx.x; e < NE; e += gridDim.x * blockDim.x)
        atomicAdd(&deg[col[e]], 1);
}

__global__ void scanA_kernel(const int* __restrict__ counts, int* __restrict__ bsum) {
    __shared__ int ws[32];
    int b = blockIdx.x, tid = threadIdx.x;
    int wid = tid >> 5, lane = tid & 31;
    int i = b * SCAN_B + tid;
    int v = (tid < SCAN_B) ? counts[i] : 0;
    #pragma unroll
    for (int o = 16; o > 0; o >>= 1) v += __shfl_down_sync(0xFFFFFFFF, v, o);
    if (lane == 0) ws[wid] = v;
    __syncthreads();
    if (wid == 0) {
        int s = ws[lane];
        #pragma unroll
        for (int o = 16; o > 0; o >>= 1) s += __shfl_down_sync(0xFFFFFFFF, s, o);
        if (lane == 0) bsum[b] = s;
    }
}

__global__ void scanB_kernel(const int* __restrict__ counts, const int* __restrict__ bsum,
                             int* __restrict__ offs) {
    __shared__ int wsum[32];
    int b = blockIdx.x, tid = threadIdx.x;
    int wid = tid >> 5, lane = tid & 31;
    int pre = 0;
    for (int q = 0; q < b; q++) pre += bsum[q];
    int i = b * SCAN_B + tid;
    int v = (tid < SCAN_B) ? counts[i] : 0;
    int x = v;
    #pragma unroll
    for (int o = 1; o < 32; o <<= 1) {
        int y = __shfl_up_sync(0xFFFFFFFF, x, o);
        if (lane >= o) x += y;
    }
    if (lane == 31) wsum[wid] = x;
    __syncthreads();
    if (wid == 0) {
        int s = wsum[lane];
        #pragma unroll
        for (int o = 1; o < 32; o <<= 1) {
            int y = __shfl_up_sync(0xFFFFFFFF, s, o);
            if (lane >= o) s += y;
        }
        wsum[lane] = s;
    }
    __syncthreads();
    int inc = x + (wid > 0 ? wsum[wid - 1] : 0);
    if (tid < SCAN_B) offs[i] = pre + inc - v;
    if (b == gridDim.x - 1 && tid == SCAN_B - 1) offs[NN] = pre + inc;
}

__global__ void fill_csr_kernel(const int* __restrict__ row, const int* __restrict__ col,
                                const int* __restrict__ offs, int* __restrict__ cursor,
                                const int* __restrict__ deg,
                                int* __restrict__ csr_src, float* __restrict__ csr_w) {
    for (int e = blockIdx.x * blockDim.x + threadIdx.x; e < NE; e += gridDim.x * blockDim.x) {
        int r = row[e], c = col[e];
        int p = atomicAdd(&cursor[c], 1);
        int slot = offs[c] + p;
        int dr = deg[r];
        float nr = (dr > 0) ? rsqrtf((float)dr) : 0.0f;
        float nc = rsqrtf((float)deg[c]);
        csr_src[slot] = r;
        csr_w[slot] = nr * nc;
    }
}

// ---------------- g0 = agg(X), 50 features -> fp16 padded to 64 ------------------
__global__ void agg0_kernel(const float* __restrict__ X, __half* __restrict__ g0h,
                            const int* __restrict__ offs, const int* __restrict__ csr_src,
                            const float* __restrict__ csr_w) {
    int node = blockIdx.x;
    int t = threadIdx.x;
    float a0 = 0.f, a1 = 0.f;
    if (t < DIN) {
        int beg = offs[node], end = offs[node + 1];
        int j = beg;
        for (; j + 1 < end; j += 2) {
            int s0 = csr_src[j], s1 = csr_src[j + 1];
            float w0 = csr_w[j], w1 = csr_w[j + 1];
            a0 = fmaf(w0, __ldg(X + (size_t)s0 * DIN + t), a0);
            a1 = fmaf(w1, __ldg(X + (size_t)s1 * DIN + t), a1);
        }
        if (j < end)
            a0 = fmaf(csr_w[j], __ldg(X + (size_t)csr_src[j] * DIN + t), a0);
    }
    g0h[(size_t)node * K1 + t] = __float2half(t < DIN ? (a0 + a1) : 0.f);
}

// ---------------- layer-1 mma GEMM ------------------------------------------------
#define RS1   144
#define ARR1  (128 * RS1)
#define G1_SMEM (2 * ARR1)

__global__ void __launch_bounds__(256, 2) mma_gemm1_kernel(
    const __half* __restrict__ A0, const __half* __restrict__ B0,
    __half* __restrict__ O, int M) {
    extern __shared__ char smem[];
    uint32_t sb = smem_u32(smem);
    int tid = threadIdx.x;
    int wid = tid >> 5, lane = tid & 31;
    int wm = wid >> 2, wn = wid & 3;
    int m0 = blockIdx.y * 128;
    int n0 = blockIdx.x * 128;

    int rrow = tid >> 1;
    int half = tid & 1;
    if (m0 + 128 > M) {
        int r = tid >> 1;
        if (m0 + r >= M) {
            uint32_t a = sb + r * RS1 + half * 64;
            #pragma unroll
            for (int q = 0; q < 4; q++)
                asm volatile("st.shared.v4.b32 [%0], {%1, %1, %1, %1};"
                             :: "r"(a + q * 16), "r"(0u) : "memory");
        }
    }
    if (m0 + rrow < M) {
        const __half* gp = A0 + (size_t)(m0 + rrow) * K1 + half * 32;
        uint32_t sa = sb + rrow * RS1 + half * 64;
        #pragma unroll
        for (int q = 0; q < 4; q++) cp16(sa + q * 16, gp + q * 8);
    }
    {
        const __half* gp = B0 + (size_t)(n0 + rrow) * K1 + half * 32;
        uint32_t sa = sb + ARR1 + rrow * RS1 + half * 64;
        #pragma unroll
        for (int q = 0; q < 4; q++) cp16(sa + q * 16, gp + q * 8);
    }
    cp_commit();
    cp_wait<0>();
    __syncthreads();

    float acc[4][4][4];
    #pragma unroll
    for (int i = 0; i < 4; i++)
        #pragma unroll
        for (int j = 0; j < 4; j++)
            #pragma unroll
            for (int q = 0; q < 4; q++) acc[i][j][q] = 0.f;

    int la = lane & 15, lha = (lane >> 4) & 1;
    int lbr = (lane & 7) + ((lane >> 4) & 1) * 8;
    int lbh = (lane >> 3) & 1;

    uint32_t aB = sb + (wm * 64) * RS1;
    uint32_t bB = sb + ARR1 + (wn * 32) * RS1;

    #pragma unroll
    for (int kk = 0; kk < 4; kk++) {
        uint32_t bh[4][2];
        #pragma unroll
        for (int pair = 0; pair < 2; pair++) {
            uint32_t bd = bB + (pair * 16 + lbr) * RS1 + lbh * 16 + kk * 32;
            uint32_t r4[4];
            ldm_x4(r4, bd);
            bh[pair * 2][0] = r4[0]; bh[pair * 2][1] = r4[1];
            bh[pair * 2 + 1][0] = r4[2]; bh[pair * 2 + 1][1] = r4[3];
        }
        #pragma unroll
        for (int im = 0; im < 4; im++) {
            uint32_t ah[4];
            uint32_t ad = aB + (im * 16 + la) * RS1 + lha * 16 + kk * 32;
            ldm_x4(ah, ad);
            #pragma unroll
            for (int in = 0; in < 4; in++)
                mma16816h(acc[im][in], ah, bh[in]);
        }
    }

    int cm = m0 + wm * 64 + (lane >> 2);
    int cn0 = n0 + wn * 32 + (lane & 3) * 2;
    #pragma unroll
    for (int im = 0; im < 4; im++) {
        #pragma unroll
        for (int hf = 0; hf < 2; hf++) {
            int r = cm + im * 16 + hf * 8;
            if (r >= M) continue;
            #pragma unroll
            for (int in = 0; in < 4; in++) {
                int c = cn0 + in * 8;
                __half2 hp = __floats2half2_rn(elu_f(acc[im][in][hf * 2 + 0]),
                                               elu_f(acc[im][in][hf * 2 + 1]));
                *(__half2*)(O + (size_t)r * K2 + HID + c) = hp;
            }
        }
    }
}

// ---------------- agg: split into 2 feature-half blocks per node ------------------
// grid 2*NN, block 128. half h covers features [1024 + h*512, 1024 + h*512 + 512).
__global__ void agg_half_kernel(__half* __restrict__ A,
                                const int* __restrict__ offs, const int* __restrict__ csr_src,
                                const float* __restrict__ csr_w) {
    int bx = blockIdx.x;
    int node = bx >> 1;
    int h = bx & 1;
    int tid = threadIdx.x;   // 0..127
    size_t cofs = HID + (size_t)h * 512 + (size_t)tid * 4;
    float a0[4] = {0.f, 0.f, 0.f, 0.f};
    float a1[4] = {0.f, 0.f, 0.f, 0.f};
    int beg = offs[node], end = offs[node + 1];
    int j = beg;
    for (; j + 1 < end; j += 2) {
        int s0 = csr_src[j], s1 = csr_src[j + 1];
        float w0 = csr_w[j], w1 = csr_w[j + 1];
        uint2 p0 = __ldg((const uint2*)(A + (size_t)s0 * K2 + cofs));
        uint2 p1 = __ldg((const uint2*)(A + (size_t)s1 * K2 + cofs));
        float2 v00 = __half22float2(*(__half2*)&p0.x);
        float2 v01 = __half22float2(*(__half2*)&p0.y);
        float2 v10 = __half22float2(*(__half2*)&p1.x);
        float2 v11 = __half22float2(*(__half2*)&p1.y);
        a0[0] = fmaf(w0, v00.x, a0[0]); a0[1] = fmaf(w0, v00.y, a0[1]);
        a0[2] = fmaf(w0, v01.x, a0[2]); a0[3] = fmaf(w0, v01.y, a0[3]);
        a1[0] = fmaf(w1, v10.x, a1[0]); a1[1] = fmaf(w1, v10.y, a1[1]);
        a1[2] = fmaf(w1, v11.x, a1[2]); a1[3] = fmaf(w1, v11.y, a1[3]);
    }
    if (j < end) {
        int s0 = csr_src[j];
        float w0 = csr_w[j];
        uint2 p0 = __ldg((const uint2*)(A + (size_t)s0 * K2 + cofs));
        float2 v00 = __half22float2(*(__half2*)&p0.x);
        float2 v01 = __half22float2(*(__half2*)&p0.y);
        a0[0] = fmaf(w0, v00.x, a0[0]); a0[1] = fmaf(w0, v00.y, a0[1]);
        a0[2] = fmaf(w0, v01.x, a0[2]); a0[3] = fmaf(w0, v01.y, a0[3]);
    }
    __half2 o01 = __floats2half2_rn(a0[0] + a1[0], a0[1] + a1[1]);
    __half2 o23 = __floats2half2_rn(a0[2] + a1[2], a0[3] + a1[3]);
    uint2 pk;
    pk.x = *(uint32_t*)&o01;
    pk.y = *(uint32_t*)&o23;
    *(uint2*)(A + (size_t)node * K2 + (size_t)h * 512 + (size_t)tid * 4) = pk;
}

// ---------------- fp16 mma.sync GEMM (K=2048, KC=64, 2 CTAs/SM) ------------------
#define KC    64
#define NCH   (K2 / KC)
#define RS    144
#define ARR_B (128 * RS)
#define STG_B (2 * ARR_B)
#define MMA_SMEM (2 * STG_B)

__device__ __forceinline__ void mma_load_chunk(
    uint32_t st, int k0,
    const __half* __restrict__ A, const __half* __restrict__ B,
    int tid, int m0, int n0, int M) {
    int rrow = tid >> 1;
    int half = tid & 1;
    {
        int grow = m0 + rrow;
        if (grow < M) {
            const __half* gp = A + (size_t)grow * K2 + k0 + half * 32;
            uint32_t sa = st + rrow * RS + half * 64;
            #pragma unroll
            for (int q = 0; q < 4; q++) cp16(sa + q * 16, gp + q * 8);
        }
    }
    {
        const __half* gp = B + (size_t)(n0 + rrow) * K2 + k0 + half * 32;
        uint32_t sa = st + ARR_B + rrow * RS + half * 64;
        #pragma unroll
        for (int q = 0; q < 4; q++) cp16(sa + q * 16, gp + q * 8);
    }
    cp_commit();
}

// MODE 0: full K, elu -> fp16 O. MODE 1: split-K half, fp32 partial to Pout.
template <int MODE>
__global__ void __launch_bounds__(256, 2) mma_gemm_kernel(
    const __half* __restrict__ Ain, const __half* __restrict__ Bin,
    __half* __restrict__ O, float* __restrict__ Pout, int M) {
    extern __shared__ char smem[];
    uint32_t sb = smem_u32(smem);
    int tid = threadIdx.x;
    int wid = tid >> 5, lane = tid & 31;
    int wm = wid >> 2, wn = wid & 3;
    int m0 = blockIdx.y * 128;
    int n0, kbase, nch;
    if (MODE == 0) { n0 = blockIdx.x * 128; kbase = 0;                 nch = NCH;     }
    else           { n0 = 0;                kbase = blockIdx.x * HID;  nch = NCH / 2; }

    if (m0 + 128 > M) {
        for (int e = tid; e < 256; e += 256) {
            int s = e >> 7, r = e & 127;
            if (m0 + r >= M) {
                uint32_t a = sb + s * STG_B + r * RS;
                #pragma unroll
                for (int q = 0; q < 8; q++)
                    asm volatile("st.shared.v4.b32 [%0], {%1, %1, %1, %1};"
                                 :: "r"(a + q * 16), "r"(0u) : "memory");
            }
        }
        __syncthreads();
    }

    float acc[4][4][4];
    #pragma unroll
    for (int i = 0; i < 4; i++)
        #pragma unroll
        for (int j = 0; j < 4; j++)
            #pragma unroll
            for (int q = 0; q < 4; q++) acc[i][j][q] = 0.f;

    mma_load_chunk(sb, kbase, Ain, Bin, tid, m0, n0, M);

    int la = lane & 15, lha = (lane >> 4) & 1;
    int lbr = (lane & 7) + ((lane >> 4) & 1) * 8;
    int lbh = (lane >> 3) & 1;

    for (int i = 0; i < nch; i++) {
        int b = i & 1;
        if (i + 1 < nch) {
            mma_load_chunk(sb + (b ^ 1) * STG_B, kbase + (i + 1) * KC, Ain, Bin,
                           tid, m0, n0, M);
            cp_wait<1>();
        } else {
            cp_wait<0>();
        }
        __syncthreads();

        uint32_t st = sb + b * STG_B;
        uint32_t aB = st + (wm * 64) * RS;
        uint32_t bB = st + ARR_B + (wn * 32) * RS;

        #pragma unroll
        for (int kk = 0; kk < 4; kk++) {
            uint32_t bh[4][2];
            #pragma unroll
            for (int pair = 0; pair < 2; pair++) {
                uint32_t bd = bB + (pair * 16 + lbr) * RS + lbh * 16 + kk * 32;
                uint32_t r4[4];
                ldm_x4(r4, bd);
                bh[pair * 2][0] = r4[0]; bh[pair * 2][1] = r4[1];
                bh[pair * 2 + 1][0] = r4[2]; bh[pair * 2 + 1][1] = r4[3];
            }
            #pragma unroll
            for (int im = 0; im < 4; im++) {
                uint32_t ah[4];
                uint32_t ad = aB + (im * 16 + la) * RS + lha * 16 + kk * 32;
                ldm_x4(ah, ad);
                #pragma unroll
                for (int in = 0; in < 4; in++)
                    mma16816h(acc[im][in], ah, bh[in]);
            }
        }
        __syncthreads();
    }

    int cm = m0 + wm * 64 + (lane >> 2);
    int cn0 = n0 + wn * 32 + (lane & 3) * 2;
    float* P = (MODE == 1) ? (Pout + (size_t)blockIdx.x * NN * NCLS) : nullptr;
    #pragma unroll
    for (int im = 0; im < 4; im++) {
        #pragma unroll
        for (int hf = 0; hf < 2; hf++) {
            int r = cm + im * 16 + hf * 8;
            if (r >= M) continue;
            #pragma unroll
            for (int in = 0; in < 4; in++) {
                int c = cn0 + in * 8;
                float v0 = acc[im][in][hf * 2 + 0];
                float v1 = acc[im][in][hf * 2 + 1];
                if (MODE == 0) {
                    __half2 hp = __floats2half2_rn(elu_f(v0), elu_f(v1));
                    *(__half2*)(O + (size_t)r * K2 + HID + c) = hp;
                } else {
                    if (c < NCLS)     P[(size_t)r * NCLS + c] = v0;
                    if (c + 1 < NCLS) P[(size_t)r * NCLS + c + 1] = v1;
                }
            }
        }
    }
}

// combine split-K partials -> d_out
__global__ void combine_kernel(const float* __restrict__ P, float* __restrict__ out) {
    int i = blockIdx.x * blockDim.x + threadIdx.x;
    if (i < NN * NCLS) out[i] = P[i] + P[(size_t)NN * NCLS + i];
}

// ---------------- launcher -------------------------------------------------------
extern "C" void kernel_launch(void* const* d_in, const int* in_sizes, int n_in,
                              void* d_out, int out_size) {
    const float* X  = (const float*)d_in[0];
    const int*   ei = (const int*)d_in[1];
    const float* W1 = (const float*)d_in[2];
    const float* W2 = (const float*)d_in[3];
    const float* S2 = (const float*)d_in[4];
    const float* W3 = (const float*)d_in[5];
    const float* S3 = (const float*)d_in[6];
    float* out = (float*)d_out;

    const int* row = ei;
    const int* col = ei + NE;

    float *w, *P;
    int *deg, *cur, *offs, *src, *bsum;
    __half *A2, *A3, *B2, *BO, *W1T, *g0h;
    cudaGetSymbolAddress((void**)&deg,  g_deg);
    cudaGetSymbolAddress((void**)&cur,  g_cursor);
    cudaGetSymbolAddress((void**)&offs, g_offs);
    cudaGetSymbolAddress((void**)&src,  g_src);
    cudaGetSymbolAddress((void**)&w,    g_w);
    cudaGetSymbolAddress((void**)&bsum, g_bsum);
    cudaGetSymbolAddress((void**)&P,    g_P);
    cudaGetSymbolAddress((void**)&A2,   g_A2);
    cudaGetSymbolAddress((void**)&A3,   g_A3);
    cudaGetSymbolAddress((void**)&B2,   g_B2);
    cudaGetSymbolAddress((void**)&BO,   g_BO);
    cudaGetSymbolAddress((void**)&W1T,  g_W1T);
    cudaGetSymbolAddress((void**)&g0h,  g_g0h);

    cudaFuncSetAttribute(mma_gemm_kernel<0>, cudaFuncAttributeMaxDynamicSharedMemorySize, MMA_SMEM);
    cudaFuncSetAttribute(mma_gemm_kernel<1>, cudaFuncAttributeMaxDynamicSharedMemorySize, MMA_SMEM);
    cudaFuncSetAttribute(mma_gemm1_kernel, cudaFuncAttributeMaxDynamicSharedMemorySize, G1_SMEM);

    static cudaStream_t s2 = nullptr;
    static cudaEvent_t evFork = nullptr, evJoin = nullptr;
    if (s2 == nullptr) {
        cudaStreamCreateWithFlags(&s2, cudaStreamNonBlocking);
        cudaEventCreateWithFlags(&evFork, cudaEventDisableTiming);
        cudaEventCreateWithFlags(&evJoin, cudaEventDisableTiming);
    }

    // ---- fork: side stream does weight prep (BO, W1T, B2) ----
    cudaEventRecord(evFork, 0);
    cudaStreamWaitEvent(s2, evFork, 0);
    prep_kernel<<<1024, 256, 0, s2>>>(W3, S3, W1, BO, W1T);
    {
        dim3 grid(32, 32, 2);
        dim3 blk(32, 8);
        transpose_w_kernel<<<grid, blk, 0, s2>>>(W2, S2, B2);
    }
    cudaEventRecord(evJoin, s2);

    // ---- main stream: CSR build + agg0 ----
    cudaMemsetAsync(deg, 0, NN * sizeof(int));
    cudaMemsetAsync(cur, 0, NN * sizeof(int));
    count_deg_kernel<<<512, 256>>>(col, deg);
    scanA_kernel<<<NN / SCAN_B, 1024>>>(deg, bsum);
    scanB_kernel<<<NN / SCAN_B, 1024>>>(deg, bsum, offs);
    fill_csr_kernel<<<512, 256>>>(row, col, offs, cur, deg, src, w);
    agg0_kernel<<<NN, 64>>>(X, g0h, offs, src, w);

    // ---- join ----
    cudaStreamWaitEvent(0, evJoin, 0);

    // h1 = elu(g0h @ W1T^T) -> A2[:,1024:]
    {
        dim3 grid(HID / 128, (NN + 127) / 128);
        mma_gemm1_kernel<<<grid, 256, G1_SMEM>>>(g0h, W1T, A2, NN);
    }
    // g1 = agg(h1) -> A2[:, 0:1024]  (2 feature-half blocks/node)
    agg_half_kernel<<<2 * NN, 128>>>(A2, offs, src, w);
    // h2 = elu([g1,h1] @ [W2;S2]) -> A3[:,1024:]
    {
        dim3 grid(HID / 128, (NN + 127) / 128);
        mma_gemm_kernel<0><<<grid, 256, MMA_SMEM>>>(A2, B2, A3, nullptr, NN);
    }
    // g2 = agg(h2) -> A3[:, 0:1024]
    agg_half_kernel<<<2 * NN, 128>>>(A3, offs, src, w);
    // split-K gemm3: partials over K halves, then combine -> d_out
    {
        dim3 grid(2, (NN + 127) / 128);
        mma_gemm_kernel<1><<<grid, 256, MMA_SMEM>>>(A3, BO, nullptr, P, NN);
    }
    combine_kernel<<<(NN * NCLS + 255) / 256, 256>>>(P, out);
}

// round 16
// speedup vs baseline: 1.5594x; 1.0336x over previous
#include <cuda_runtime.h>
#include <cuda_bf16.h>
#include <cuda_fp16.h>
#include <math.h>
#include <cstdint>

// Problem constants
#define NN   20000
#define NE   320000
#define DIN  50
#define K1   64
#define HID  1024
#define F3   726
#define NCLS 121
#define K2   2048
#define NOUT 128
#define SCAN_B 1000

// ---------------- scratch (device globals) -------------------------------------
__device__ __align__(128) __half g_A2[(size_t)NN * K2];   // [g1 | h1] fp16
__device__ __align__(128) __half g_A3[(size_t)NN * K2];   // [g2 | h2] fp16
__device__ __align__(128) __half g_B2[(size_t)HID * K2];  // [W2;S2]^T fp16
__device__ __align__(128) __half g_BO[(size_t)NOUT * K2]; // [W3m;S3m]^T fp16
__device__ __align__(128) __half g_W1T[(size_t)HID * K1];
__device__ __align__(128) __half g_g0h[(size_t)NN * K1];
__device__ __align__(128) float g_P[2 * (size_t)NN * NCLS]; // split-K partials
__device__ int   g_deg[NN];
__device__ int   g_cursor[NN];
__device__ int   g_offs[NN + 1];
__device__ int   g_src[NE];
__device__ float g_w[NE];
__device__ int   g_bsum[32];

// ================= PTX helpers =================================================
__device__ __forceinline__ uint32_t smem_u32(const void* p) {
    uint32_t a;
    asm("{ .reg .u64 t; cvta.to.shared.u64 t, %1; cvt.u32.u64 %0, t; }" : "=r"(a) : "l"(p));
    return a;
}
__device__ __forceinline__ void cp16(uint32_t dst, const void* src) {
    uint64_t g = __cvta_generic_to_global(src);
    asm volatile("cp.async.cg.shared.global [%0], [%1], 16;" :: "r"(dst), "l"(g));
}
__device__ __forceinline__ void cp_commit() { asm volatile("cp.async.commit_group;" ::: "memory"); }
template <int N> __device__ __forceinline__ void cp_wait() {
    asm volatile("cp.async.wait_group %0;" :: "n"(N) : "memory");
}
__device__ __forceinline__ void ldm_x4(uint32_t* r, uint32_t addr) {
    asm volatile("ldmatrix.sync.aligned.m8n8.x4.shared.b16 {%0,%1,%2,%3}, [%4];"
                 : "=r"(r[0]), "=r"(r[1]), "=r"(r[2]), "=r"(r[3]) : "r"(addr));
}
__device__ __forceinline__ void mma16816h(float* c, const uint32_t* a, const uint32_t* b) {
    asm volatile(
        "mma.sync.aligned.m16n8k16.row.col.f32.f16.f16.f32 "
        "{%0,%1,%2,%3}, {%4,%5,%6,%7}, {%8,%9}, {%0,%1,%2,%3};"
        : "+f"(c[0]), "+f"(c[1]), "+f"(c[2]), "+f"(c[3])
        : "r"(a[0]), "r"(a[1]), "r"(a[2]), "r"(a[3]), "r"(b[0]), "r"(b[1]));
}

// elu via fast exp (MUFU.EX2): rel err ~1e-6, far under the 1e-3 gate
__device__ __forceinline__ float elu_f(float x) {
    return x > 0.f ? x : (__expf(x) - 1.f);
}

// ---------------- prep: BO weights + W1 transpose --------------------------------
__global__ void prep_kernel(const float* __restrict__ W3, const float* __restrict__ S3,
                            const float* __restrict__ W1,
                            __half* __restrict__ BO, __half* __restrict__ W1T) {
    int i = blockIdx.x * blockDim.x + threadIdx.x;
    int stride = gridDim.x * blockDim.x;
    for (int j = i; j < NOUT * K2; j += stride) {
        int n = j >> 11, k = j & (K2 - 1);
        float v = 0.f;
        if (n < NCLS) {
            const float* Wp = (k < HID) ? (W3 + (size_t)k * F3) : (S3 + (size_t)(k - HID) * F3);
            #pragma unroll
            for (int hh = 0; hh < 6; hh++) v += Wp[hh * NCLS + n];
            v *= (1.0f / 6.0f);
        }
        BO[j] = __float2half(v);
    }
    for (int j = i; j < HID * K1; j += stride) {
        int n = j >> 6, k = j & (K1 - 1);
        float v = (k < DIN) ? W1[(size_t)k * HID + n] : 0.f;
        W1T[j] = __float2half(v);
    }
}

// ---------------- tiled transpose: W2/S2 [1024,1024] fp32 -> B2 [n][2048] fp16 ---
__global__ void transpose_w_kernel(const float* __restrict__ W2, const float* __restrict__ S2,
                                   __half* __restrict__ B2) {
    __shared__ float tile[32][33];
    const float* W = (blockIdx.z == 0) ? W2 : S2;
    int koff = blockIdx.z * HID;
    int k0 = blockIdx.x * 32;
    int n0 = blockIdx.y * 32;
    int tx = threadIdx.x, ty = threadIdx.y;
    #pragma unroll
    for (int r = 0; r < 4; r++) {
        int k = k0 + ty + r * 8;
        tile[ty + r * 8][tx] = W[(size_t)k * HID + n0 + tx];
    }
    __syncthreads();
    #pragma unroll
    for (int r = 0; r < 4; r++) {
        int n = n0 + ty + r * 8;
        B2[(size_t)n * K2 + koff + k0 + tx] = __float2half(tile[tx][ty + r * 8]);
    }
}

// ---------------- CSR build ------------------------------------------------------
__global__ void count_deg_kernel(const int* __restrict__ col, int* __restrict__ deg) {
    for (int e = blockIdx.x * blockDim.x + threadIdx.x; e < NE; e += gridDim.x * blockDim.x)
        atomicAdd(&deg[col[e]], 1);
}

__global__ void scanA_kernel(const int* __restrict__ counts, int* __restrict__ bsum) {
    __shared__ int ws[32];
    int b = blockIdx.x, tid = threadIdx.x;
    int wid = tid >> 5, lane = tid & 31;
    int i = b * SCAN_B + tid;
    int v = (tid < SCAN_B) ? counts[i] : 0;
    #pragma unroll
    for (int o = 16; o > 0; o >>= 1) v += __shfl_down_sync(0xFFFFFFFF, v, o);
    if (lane == 0) ws[wid] = v;
    __syncthreads();
    if (wid == 0) {
        int s = ws[lane];
        #pragma unroll
        for (int o = 16; o > 0; o >>= 1) s += __shfl_down_sync(0xFFFFFFFF, s, o);
        if (lane == 0) bsum[b] = s;
    }
}

__global__ void scanB_kernel(const int* __restrict__ counts, const int* __restrict__ bsum,
                             int* __restrict__ offs) {
    __shared__ int wsum[32];
    int b = blockIdx.x, tid = threadIdx.x;
    int wid = tid >> 5, lane = tid & 31;
    int pre = 0;
    for (int q = 0; q < b; q++) pre += bsum[q];
    int i = b * SCAN_B + tid;
    int v = (tid < SCAN_B) ? counts[i] : 0;
    int x = v;
    #pragma unroll
    for (int o = 1; o < 32; o <<= 1) {
        int y = __shfl_up_sync(0xFFFFFFFF, x, o);
        if (lane >= o) x += y;
    }
    if (lane == 31) wsum[wid] = x;
    __syncthreads();
    if (wid == 0) {
        int s = wsum[lane];
        #pragma unroll
        for (int o = 1; o < 32; o <<= 1) {
            int y = __shfl_up_sync(0xFFFFFFFF, s, o);
            if (lane >= o) s += y;
        }
        wsum[lane] = s;
    }
    __syncthreads();
    int inc = x + (wid > 0 ? wsum[wid - 1] : 0);
    if (tid < SCAN_B) offs[i] = pre + inc - v;
    if (b == gridDim.x - 1 && tid == SCAN_B - 1) offs[NN] = pre + inc;
}

__global__ void fill_csr_kernel(const int* __restrict__ row, const int* __restrict__ col,
                                const int* __restrict__ offs, int* __restrict__ cursor,
                                const int* __restrict__ deg,
                                int* __restrict__ csr_src, float* __restrict__ csr_w) {
    for (int e = blockIdx.x * blockDim.x + threadIdx.x; e < NE; e += gridDim.x * blockDim.x) {
        int r = row[e], c = col[e];
        int p = atomicAdd(&cursor[c], 1);
        int slot = offs[c] + p;
        int dr = deg[r];
        float nr = (dr > 0) ? rsqrtf((float)dr) : 0.0f;
        float nc = rsqrtf((float)deg[c]);
        csr_src[slot] = r;
        csr_w[slot] = nr * nc;
    }
}

// ---------------- g0 = agg(X), 50 features -> fp16 padded to 64 ------------------
__global__ void agg0_kernel(const float* __restrict__ X, __half* __restrict__ g0h,
                            const int* __restrict__ offs, const int* __restrict__ csr_src,
                            const float* __restrict__ csr_w) {
    int node = blockIdx.x;
    int t = threadIdx.x;
    float a0 = 0.f, a1 = 0.f;
    if (t < DIN) {
        int beg = offs[node], end = offs[node + 1];
        int j = beg;
        for (; j + 1 < end; j += 2) {
            int s0 = csr_src[j], s1 = csr_src[j + 1];
            float w0 = csr_w[j], w1 = csr_w[j + 1];
            a0 = fmaf(w0, __ldg(X + (size_t)s0 * DIN + t), a0);
            a1 = fmaf(w1, __ldg(X + (size_t)s1 * DIN + t), a1);
        }
        if (j < end)
            a0 = fmaf(csr_w[j], __ldg(X + (size_t)csr_src[j] * DIN + t), a0);
    }
    g0h[(size_t)node * K1 + t] = __float2half(t < DIN ? (a0 + a1) : 0.f);
}

// ---------------- layer-1 mma GEMM ------------------------------------------------
#define RS1   144
#define ARR1  (128 * RS1)
#define G1_SMEM (2 * ARR1)

__global__ void __launch_bounds__(256, 2) mma_gemm1_kernel(
    const __half* __restrict__ A0, const __half* __restrict__ B0,
    __half* __restrict__ O, int M) {
    extern __shared__ char smem[];
    uint32_t sb = smem_u32(smem);
    int tid = threadIdx.x;
    int wid = tid >> 5, lane = tid & 31;
    int wm = wid >> 2, wn = wid & 3;
    int m0 = blockIdx.y * 128;
    int n0 = blockIdx.x * 128;

    int rrow = tid >> 1;
    int half = tid & 1;
    if (m0 + 128 > M) {
        int r = tid >> 1;
        if (m0 + r >= M) {
            uint32_t a = sb + r * RS1 + half * 64;
            #pragma unroll
            for (int q = 0; q < 4; q++)
                asm volatile("st.shared.v4.b32 [%0], {%1, %1, %1, %1};"
                             :: "r"(a + q * 16), "r"(0u) : "memory");
        }
    }
    if (m0 + rrow < M) {
        const __half* gp = A0 + (size_t)(m0 + rrow) * K1 + half * 32;
        uint32_t sa = sb + rrow * RS1 + half * 64;
        #pragma unroll
        for (int q = 0; q < 4; q++) cp16(sa + q * 16, gp + q * 8);
    }
    {
        const __half* gp = B0 + (size_t)(n0 + rrow) * K1 + half * 32;
        uint32_t sa = sb + ARR1 + rrow * RS1 + half * 64;
        #pragma unroll
        for (int q = 0; q < 4; q++) cp16(sa + q * 16, gp + q * 8);
    }
    cp_commit();
    cp_wait<0>();
    __syncthreads();

    float acc[4][4][4];
    #pragma unroll
    for (int i = 0; i < 4; i++)
        #pragma unroll
        for (int j = 0; j < 4; j++)
            #pragma unroll
            for (int q = 0; q < 4; q++) acc[i][j][q] = 0.f;

    int la = lane & 15, lha = (lane >> 4) & 1;
    int lbr = (lane & 7) + ((lane >> 4) & 1) * 8;
    int lbh = (lane >> 3) & 1;

    uint32_t aB = sb + (wm * 64) * RS1;
    uint32_t bB = sb + ARR1 + (wn * 32) * RS1;

    #pragma unroll
    for (int kk = 0; kk < 4; kk++) {
        uint32_t bh[4][2];
        #pragma unroll
        for (int pair = 0; pair < 2; pair++) {
            uint32_t bd = bB + (pair * 16 + lbr) * RS1 + lbh * 16 + kk * 32;
            uint32_t r4[4];
            ldm_x4(r4, bd);
            bh[pair * 2][0] = r4[0]; bh[pair * 2][1] = r4[1];
            bh[pair * 2 + 1][0] = r4[2]; bh[pair * 2 + 1][1] = r4[3];
        }
        #pragma unroll
        for (int im = 0; im < 4; im++) {
            uint32_t ah[4];
            uint32_t ad = aB + (im * 16 + la) * RS1 + lha * 16 + kk * 32;
            ldm_x4(ah, ad);
            #pragma unroll
            for (int in = 0; in < 4; in++)
                mma16816h(acc[im][in], ah, bh[in]);
        }
    }

    int cm = m0 + wm * 64 + (lane >> 2);
    int cn0 = n0 + wn * 32 + (lane & 3) * 2;
    #pragma unroll
    for (int im = 0; im < 4; im++) {
        #pragma unroll
        for (int hf = 0; hf < 2; hf++) {
            int r = cm + im * 16 + hf * 8;
            if (r >= M) continue;
            #pragma unroll
            for (int in = 0; in < 4; in++) {
                int c = cn0 + in * 8;
                __half2 hp = __floats2half2_rn(elu_f(acc[im][in][hf * 2 + 0]),
                                               elu_f(acc[im][in][hf * 2 + 1]));
                *(__half2*)(O + (size_t)r * K2 + HID + c) = hp;
            }
        }
    }
}

// ---------------- agg: split into 2 feature-half blocks per node ------------------
__global__ void agg_half_kernel(__half* __restrict__ A,
                                const int* __restrict__ offs, const int* __restrict__ csr_src,
                                const float* __restrict__ csr_w) {
    int bx = blockIdx.x;
    int node = bx >> 1;
    int h = bx & 1;
    int tid = threadIdx.x;   // 0..127
    size_t cofs = HID + (size_t)h * 512 + (size_t)tid * 4;
    float a0[4] = {0.f, 0.f, 0.f, 0.f};
    float a1[4] = {0.f, 0.f, 0.f, 0.f};
    int beg = offs[node], end = offs[node + 1];
    int j = beg;
    for (; j + 1 < end; j += 2) {
        int s0 = csr_src[j], s1 = csr_src[j + 1];
        float w0 = csr_w[j], w1 = csr_w[j + 1];
        uint2 p0 = __ldg((const uint2*)(A + (size_t)s0 * K2 + cofs));
        uint2 p1 = __ldg((const uint2*)(A + (size_t)s1 * K2 + cofs));
        float2 v00 = __half22float2(*(__half2*)&p0.x);
        float2 v01 = __half22float2(*(__half2*)&p0.y);
        float2 v10 = __half22float2(*(__half2*)&p1.x);
        float2 v11 = __half22float2(*(__half2*)&p1.y);
        a0[0] = fmaf(w0, v00.x, a0[0]); a0[1] = fmaf(w0, v00.y, a0[1]);
        a0[2] = fmaf(w0, v01.x, a0[2]); a0[3] = fmaf(w0, v01.y, a0[3]);
        a1[0] = fmaf(w1, v10.x, a1[0]); a1[1] = fmaf(w1, v10.y, a1[1]);
        a1[2] = fmaf(w1, v11.x, a1[2]); a1[3] = fmaf(w1, v11.y, a1[3]);
    }
    if (j < end) {
        int s0 = csr_src[j];
        float w0 = csr_w[j];
        uint2 p0 = __ldg((const uint2*)(A + (size_t)s0 * K2 + cofs));
        float2 v00 = __half22float2(*(__half2*)&p0.x);
        float2 v01 = __half22float2(*(__half2*)&p0.y);
        a0[0] = fmaf(w0, v00.x, a0[0]); a0[1] = fmaf(w0, v00.y, a0[1]);
        a0[2] = fmaf(w0, v01.x, a0[2]); a0[3] = fmaf(w0, v01.y, a0[3]);
    }
    __half2 o01 = __floats2half2_rn(a0[0] + a1[0], a0[1] + a1[1]);
    __half2 o23 = __floats2half2_rn(a0[2] + a1[2], a0[3] + a1[3]);
    uint2 pk;
    pk.x = *(uint32_t*)&o01;
    pk.y = *(uint32_t*)&o23;
    *(uint2*)(A + (size_t)node * K2 + (size_t)h * 512 + (size_t)tid * 4) = pk;
}

// ---------------- fp16 mma.sync GEMM (K=2048, KC=64, 2 CTAs/SM) ------------------
#define KC    64
#define NCH   (K2 / KC)
#define RS    144
#define ARR_B (128 * RS)
#define STG_B (2 * ARR_B)
#define MMA_SMEM (2 * STG_B)

__device__ __forceinline__ void mma_load_chunk(
    uint32_t st, int k0,
    const __half* __restrict__ A, const __half* __restrict__ B,
    int tid, int m0, int n0, int M) {
    int rrow = tid >> 1;
    int half = tid & 1;
    {
        int grow = m0 + rrow;
        if (grow < M) {
            const __half* gp = A + (size_t)grow * K2 + k0 + half * 32;
            uint32_t sa = st + rrow * RS + half * 64;
            #pragma unroll
            for (int q = 0; q < 4; q++) cp16(sa + q * 16, gp + q * 8);
        }
    }
    {
        const __half* gp = B + (size_t)(n0 + rrow) * K2 + k0 + half * 32;
        uint32_t sa = st + ARR_B + rrow * RS + half * 64;
        #pragma unroll
        for (int q = 0; q < 4; q++) cp16(sa + q * 16, gp + q * 8);
    }
    cp_commit();
}

// MODE 0: full K, elu -> fp16 O. MODE 1: split-K half, fp32 partial to Pout.
template <int MODE>
__global__ void __launch_bounds__(256, 2) mma_gemm_kernel(
    const __half* __restrict__ Ain, const __half* __restrict__ Bin,
    __half* __restrict__ O, float* __restrict__ Pout, int M) {
    extern __shared__ char smem[];
    uint32_t sb = smem_u32(smem);
    int tid = threadIdx.x;
    int wid = tid >> 5, lane = tid & 31;
    int wm = wid >> 2, wn = wid & 3;
    int m0 = blockIdx.y * 128;
    int n0, kbase, nch;
    if (MODE == 0) { n0 = blockIdx.x * 128; kbase = 0;                 nch = NCH;     }
    else           { n0 = 0;                kbase = blockIdx.x * HID;  nch = NCH / 2; }

    if (m0 + 128 > M) {
        for (int e = tid; e < 256; e += 256) {
            int s = e >> 7, r = e & 127;
            if (m0 + r >= M) {
                uint32_t a = sb + s * STG_B + r * RS;
                #pragma unroll
                for (int q = 0; q < 8; q++)
                    asm volatile("st.shared.v4.b32 [%0], {%1, %1, %1, %1};"
                                 :: "r"(a + q * 16), "r"(0u) : "memory");
            }
        }
        __syncthreads();
    }

    float acc[4][4][4];
    #pragma unroll
    for (int i = 0; i < 4; i++)
        #pragma unroll
        for (int j = 0; j < 4; j++)
            #pragma unroll
            for (int q = 0; q < 4; q++) acc[i][j][q] = 0.f;

    mma_load_chunk(sb, kbase, Ain, Bin, tid, m0, n0, M);

    int la = lane & 15, lha = (lane >> 4) & 1;
    int lbr = (lane & 7) + ((lane >> 4) & 1) * 8;
    int lbh = (lane >> 3) & 1;

    for (int i = 0; i < nch; i++) {
        int b = i & 1;
        if (i + 1 < nch) {
            mma_load_chunk(sb + (b ^ 1) * STG_B, kbase + (i + 1) * KC, Ain, Bin,
                           tid, m0, n0, M);
            cp_wait<1>();
        } else {
            cp_wait<0>();
        }
        __syncthreads();

        uint32_t st = sb + b * STG_B;
        uint32_t aB = st + (wm * 64) * RS;
        uint32_t bB = st + ARR_B + (wn * 32) * RS;

        #pragma unroll
        for (int kk = 0; kk < 4; kk++) {
            uint32_t bh[4][2];
            #pragma unroll
            for (int pair = 0; pair < 2; pair++) {
                uint32_t bd = bB + (pair * 16 + lbr) * RS + lbh * 16 + kk * 32;
                uint32_t r4[4];
                ldm_x4(r4, bd);
                bh[pair * 2][0] = r4[0]; bh[pair * 2][1] = r4[1];
                bh[pair * 2 + 1][0] = r4[2]; bh[pair * 2 + 1][1] = r4[3];
            }
            #pragma unroll
            for (int im = 0; im < 4; im++) {
                uint32_t ah[4];
                uint32_t ad = aB + (im * 16 + la) * RS + lha * 16 + kk * 32;
                ldm_x4(ah, ad);
                #pragma unroll
                for (int in = 0; in < 4; in++)
                    mma16816h(acc[im][in], ah, bh[in]);
            }
        }
        __syncthreads();
    }

    int cm = m0 + wm * 64 + (lane >> 2);
    int cn0 = n0 + wn * 32 + (lane & 3) * 2;
    float* P = (MODE == 1) ? (Pout + (size_t)blockIdx.x * NN * NCLS) : nullptr;
    #pragma unroll
    for (int im = 0; im < 4; im++) {
        #pragma unroll
        for (int hf = 0; hf < 2; hf++) {
            int r = cm + im * 16 + hf * 8;
            if (r >= M) continue;
            #pragma unroll
            for (int in = 0; in < 4; in++) {
                int c = cn0 + in * 8;
                float v0 = acc[im][in][hf * 2 + 0];
                float v1 = acc[im][in][hf * 2 + 1];
                if (MODE == 0) {
                    __half2 hp = __floats2half2_rn(elu_f(v0), elu_f(v1));
                    *(__half2*)(O + (size_t)r * K2 + HID + c) = hp;
                } else {
                    if (c < NCLS)     P[(size_t)r * NCLS + c] = v0;
                    if (c + 1 < NCLS) P[(size_t)r * NCLS + c + 1] = v1;
                }
            }
        }
    }
}

// combine split-K partials -> d_out
__global__ void combine_kernel(const float* __restrict__ P, float* __restrict__ out) {
    int i = blockIdx.x * blockDim.x + threadIdx.x;
    if (i < NN * NCLS) out[i] = P[i] + P[(size_t)NN * NCLS + i];
}

// ---------------- launcher -------------------------------------------------------
extern "C" void kernel_launch(void* const* d_in, const int* in_sizes, int n_in,
                              void* d_out, int out_size) {
    const float* X  = (const float*)d_in[0];
    const int*   ei = (const int*)d_in[1];
    const float* W1 = (const float*)d_in[2];
    const float* W2 = (const float*)d_in[3];
    const float* S2 = (const float*)d_in[4];
    const float* W3 = (const float*)d_in[5];
    const float* S3 = (const float*)d_in[6];
    float* out = (float*)d_out;

    const int* row = ei;
    const int* col = ei + NE;

    float *w, *P;
    int *deg, *cur, *offs, *src, *bsum;
    __half *A2, *A3, *B2, *BO, *W1T, *g0h;
    cudaGetSymbolAddress((void**)&deg,  g_deg);
    cudaGetSymbolAddress((void**)&cur,  g_cursor);
    cudaGetSymbolAddress((void**)&offs, g_offs);
    cudaGetSymbolAddress((void**)&src,  g_src);
    cudaGetSymbolAddress((void**)&w,    g_w);
    cudaGetSymbolAddress((void**)&bsum, g_bsum);
    cudaGetSymbolAddress((void**)&P,    g_P);
    cudaGetSymbolAddress((void**)&A2,   g_A2);
    cudaGetSymbolAddress((void**)&A3,   g_A3);
    cudaGetSymbolAddress((void**)&B2,   g_B2);
    cudaGetSymbolAddress((void**)&BO,   g_BO);
    cudaGetSymbolAddress((void**)&W1T,  g_W1T);
    cudaGetSymbolAddress((void**)&g0h,  g_g0h);

    cudaFuncSetAttribute(mma_gemm_kernel<0>, cudaFuncAttributeMaxDynamicSharedMemorySize, MMA_SMEM);
    cudaFuncSetAttribute(mma_gemm_kernel<1>, cudaFuncAttributeMaxDynamicSharedMemorySize, MMA_SMEM);
    cudaFuncSetAttribute(mma_gemm1_kernel, cudaFuncAttributeMaxDynamicSharedMemorySize, G1_SMEM);

    static cudaStream_t s2 = nullptr;
    static cudaEvent_t evFork = nullptr, evJoin = nullptr;
    if (s2 == nullptr) {
        cudaStreamCreateWithFlags(&s2, cudaStreamNonBlocking);
        cudaEventCreateWithFlags(&evFork, cudaEventDisableTiming);
        cudaEventCreateWithFlags(&evJoin, cudaEventDisableTiming);
    }

    // ---- fork: side stream does weight prep (BO, W1T, B2) ----
    cudaEventRecord(evFork, 0);
    cudaStreamWaitEvent(s2, evFork, 0);
    prep_kernel<<<1024, 256, 0, s2>>>(W3, S3, W1, BO, W1T);
    {
        dim3 grid(32, 32, 2);
        dim3 blk(32, 8);
        transpose_w_kernel<<<grid, blk, 0, s2>>>(W2, S2, B2);
    }
    cudaEventRecord(evJoin, s2);

    // ---- main stream: CSR build + agg0 ----
    cudaMemsetAsync(deg, 0, NN * sizeof(int));
    cudaMemsetAsync(cur, 0, NN * sizeof(int));
    count_deg_kernel<<<512, 256>>>(col, deg);
    scanA_kernel<<<NN / SCAN_B, 1024>>>(deg, bsum);
    scanB_kernel<<<NN / SCAN_B, 1024>>>(deg, bsum, offs);
    fill_csr_kernel<<<512, 256>>>(row, col, offs, cur, deg, src, w);
    agg0_kernel<<<NN, 64>>>(X, g0h, offs, src, w);

    // ---- join ----
    cudaStreamWaitEvent(0, evJoin, 0);

    // h1 = elu(g0h @ W1T^T) -> A2[:,1024:]
    {
        dim3 grid(HID / 128, (NN + 127) / 128);
        mma_gemm1_kernel<<<grid, 256, G1_SMEM>>>(g0h, W1T, A2, NN);
    }
    // g1 = agg(h1) -> A2[:, 0:1024]
    agg_half_kernel<<<2 * NN, 128>>>(A2, offs, src, w);
    // h2 = elu([g1,h1] @ [W2;S2]) -> A3[:,1024:]
    {
        dim3 grid(HID / 128, (NN + 127) / 128);
        mma_gemm_kernel<0><<<grid, 256, MMA_SMEM>>>(A2, B2, A3, nullptr, NN);
    }
    // g2 = agg(h2) -> A3[:, 0:1024]
    agg_half_kernel<<<2 * NN, 128>>>(A3, offs, src, w);
    // split-K gemm3 + combine -> d_out
    {
        dim3 grid(2, (NN + 127) / 128);
        mma_gemm_kernel<1><<<grid, 256, MMA_SMEM>>>(A3, BO, nullptr, P, NN);
    }
    combine_kernel<<<(NN * NCLS + 255) / 256, 256>>>(P, out);
}

// round 17
// speedup vs baseline: 1.5876x; 1.0181x over previous
#include <cuda_runtime.h>
#include <cuda_bf16.h>
#include <cuda_fp16.h>
#include <math.h>
#include <cstdint>

// Problem constants
#define NN   20000
#define NE   320000
#define DIN  50
#define K1   64
#define HID  1024
#define F3   726
#define NCLS 121
#define K2   2048
#define NOUT 128
#define SCAN_B 1000

// ---------------- scratch (device globals) -------------------------------------
__device__ __align__(128) __half g_A2[(size_t)NN * K2];   // [g1 | h1] fp16
__device__ __align__(128) __half g_A3[(size_t)NN * K2];   // [g2 | h2] fp16
__device__ __align__(128) __half g_B2[(size_t)HID * K2];  // [W2;S2]^T fp16
__device__ __align__(128) __half g_BO[(size_t)NOUT * K2]; // [W3m;S3m]^T fp16
__device__ __align__(128) __half g_W1T[(size_t)HID * K1];
__device__ __align__(128) __half g_g0h[(size_t)NN * K1];
__device__ __align__(128) float g_P[2 * (size_t)NN * NCLS]; // split-K partials
__device__ int   g_deg[NN];
__device__ int   g_cursor[NN];
__device__ int   g_offs[NN + 1];
__device__ int   g_src[NE];
__device__ float g_w[NE];
__device__ int   g_bsum[32];

// ================= PTX helpers =================================================
__device__ __forceinline__ uint32_t smem_u32(const void* p) {
    uint32_t a;
    asm("{ .reg .u64 t; cvta.to.shared.u64 t, %1; cvt.u32.u64 %0, t; }" : "=r"(a) : "l"(p));
    return a;
}
__device__ __forceinline__ void cp16(uint32_t dst, const void* src) {
    uint64_t g = __cvta_generic_to_global(src);
    asm volatile("cp.async.cg.shared.global [%0], [%1], 16;" :: "r"(dst), "l"(g));
}
__device__ __forceinline__ void cp_commit() { asm volatile("cp.async.commit_group;" ::: "memory"); }
template <int N> __device__ __forceinline__ void cp_wait() {
    asm volatile("cp.async.wait_group %0;" :: "n"(N) : "memory");
}
__device__ __forceinline__ void ldm_x4(uint32_t* r, uint32_t addr) {
    asm volatile("ldmatrix.sync.aligned.m8n8.x4.shared.b16 {%0,%1,%2,%3}, [%4];"
                 : "=r"(r[0]), "=r"(r[1]), "=r"(r[2]), "=r"(r[3]) : "r"(addr));
}
__device__ __forceinline__ void mma16816h(float* c, const uint32_t* a, const uint32_t* b) {
    asm volatile(
        "mma.sync.aligned.m16n8k16.row.col.f32.f16.f16.f32 "
        "{%0,%1,%2,%3}, {%4,%5,%6,%7}, {%8,%9}, {%0,%1,%2,%3};"
        : "+f"(c[0]), "+f"(c[1]), "+f"(c[2]), "+f"(c[3])
        : "r"(a[0]), "r"(a[1]), "r"(a[2]), "r"(a[3]), "r"(b[0]), "r"(b[1]));
}

// elu via fast exp (MUFU.EX2)
__device__ __forceinline__ float elu_f(float x) {
    return x > 0.f ? x : (__expf(x) - 1.f);
}

// ---------------- prep: BO weights + W1 transpose --------------------------------
__global__ void prep_kernel(const float* __restrict__ W3, const float* __restrict__ S3,
                            const float* __restrict__ W1,
                            __half* __restrict__ BO, __half* __restrict__ W1T) {
    int i = blockIdx.x * blockDim.x + threadIdx.x;
    int stride = gridDim.x * blockDim.x;
    for (int j = i; j < NOUT * K2; j += stride) {
        int n = j >> 11, k = j & (K2 - 1);
        float v = 0.f;
        if (n < NCLS) {
            const float* Wp = (k < HID) ? (W3 + (size_t)k * F3) : (S3 + (size_t)(k - HID) * F3);
            #pragma unroll
            for (int hh = 0; hh < 6; hh++) v += Wp[hh * NCLS + n];
            v *= (1.0f / 6.0f);
        }
        BO[j] = __float2half(v);
    }
    for (int j = i; j < HID * K1; j += stride) {
        int n = j >> 6, k = j & (K1 - 1);
        float v = (k < DIN) ? W1[(size_t)k * HID + n] : 0.f;
        W1T[j] = __float2half(v);
    }
}

// ---------------- tiled transpose: W2/S2 [1024,1024] fp32 -> B2 [n][2048] fp16 ---
__global__ void transpose_w_kernel(const float* __restrict__ W2, const float* __restrict__ S2,
                                   __half* __restrict__ B2) {
    __shared__ float tile[32][33];
    const float* W = (blockIdx.z == 0) ? W2 : S2;
    int koff = blockIdx.z * HID;
    int k0 = blockIdx.x * 32;
    int n0 = blockIdx.y * 32;
    int tx = threadIdx.x, ty = threadIdx.y;
    #pragma unroll
    for (int r = 0; r < 4; r++) {
        int k = k0 + ty + r * 8;
        tile[ty + r * 8][tx] = W[(size_t)k * HID + n0 + tx];
    }
    __syncthreads();
    #pragma unroll
    for (int r = 0; r < 4; r++) {
        int n = n0 + ty + r * 8;
        B2[(size_t)n * K2 + koff + k0 + tx] = __float2half(tile[tx][ty + r * 8]);
    }
}

// ---------------- CSR build ------------------------------------------------------
__global__ void count_deg_kernel(const int* __restrict__ col, int* __restrict__ deg) {
    for (int e = blockIdx.x * blockDim.x + threadIdx.x; e < NE; e += gridDim.x * blockDim.x)
        atomicAdd(&deg[col[e]], 1);
}

__global__ void scanA_kernel(const int* __restrict__ counts, int* __restrict__ bsum) {
    __shared__ int ws[32];
    int b = blockIdx.x, tid = threadIdx.x;
    int wid = tid >> 5, lane = tid & 31;
    int i = b * SCAN_B + tid;
    int v = (tid < SCAN_B) ? counts[i] : 0;
    #pragma unroll
    for (int o = 16; o > 0; o >>= 1) v += __shfl_down_sync(0xFFFFFFFF, v, o);
    if (lane == 0) ws[wid] = v;
    __syncthreads();
    if (wid == 0) {
        int s = ws[lane];
        #pragma unroll
        for (int o = 16; o > 0; o >>= 1) s += __shfl_down_sync(0xFFFFFFFF, s, o);
        if (lane == 0) bsum[b] = s;
    }
}

__global__ void scanB_kernel(const int* __restrict__ counts, const int* __restrict__ bsum,
                             int* __restrict__ offs) {
    __shared__ int wsum[32];
    int b = blockIdx.x, tid = threadIdx.x;
    int wid = tid >> 5, lane = tid & 31;
    int pre = 0;
    for (int q = 0; q < b; q++) pre += bsum[q];
    int i = b * SCAN_B + tid;
    int v = (tid < SCAN_B) ? counts[i] : 0;
    int x = v;
    #pragma unroll
    for (int o = 1; o < 32; o <<= 1) {
        int y = __shfl_up_sync(0xFFFFFFFF, x, o);
        if (lane >= o) x += y;
    }
    if (lane == 31) wsum[wid] = x;
    __syncthreads();
    if (wid == 0) {
        int s = wsum[lane];
        #pragma unroll
        for (int o = 1; o < 32; o <<= 1) {
            int y = __shfl_up_sync(0xFFFFFFFF, s, o);
            if (lane >= o) s += y;
        }
        wsum[lane] = s;
    }
    __syncthreads();
    int inc = x + (wid > 0 ? wsum[wid - 1] : 0);
    if (tid < SCAN_B) offs[i] = pre + inc - v;
    if (b == gridDim.x - 1 && tid == SCAN_B - 1) offs[NN] = pre + inc;
}

__global__ void fill_csr_kernel(const int* __restrict__ row, const int* __restrict__ col,
                                const int* __restrict__ offs, int* __restrict__ cursor,
                                const int* __restrict__ deg,
                                int* __restrict__ csr_src, float* __restrict__ csr_w) {
    for (int e = blockIdx.x * blockDim.x + threadIdx.x; e < NE; e += gridDim.x * blockDim.x) {
        int r = row[e], c = col[e];
        int p = atomicAdd(&cursor[c], 1);
        int slot = offs[c] + p;
        int dr = deg[r];
        float nr = (dr > 0) ? rsqrtf((float)dr) : 0.0f;
        float nc = rsqrtf((float)deg[c]);
        csr_src[slot] = r;
        csr_w[slot] = nr * nc;
    }
}

// ---------------- g0 = agg(X), 50 features -> fp16 padded to 64 ------------------
__global__ void agg0_kernel(const float* __restrict__ X, __half* __restrict__ g0h,
                            const int* __restrict__ offs, const int* __restrict__ csr_src,
                            const float* __restrict__ csr_w) {
    int node = blockIdx.x;
    int t = threadIdx.x;
    float a0 = 0.f, a1 = 0.f;
    if (t < DIN) {
        int beg = offs[node], end = offs[node + 1];
        int j = beg;
        for (; j + 1 < end; j += 2) {
            int s0 = csr_src[j], s1 = csr_src[j + 1];
            float w0 = csr_w[j], w1 = csr_w[j + 1];
            a0 = fmaf(w0, __ldg(X + (size_t)s0 * DIN + t), a0);
            a1 = fmaf(w1, __ldg(X + (size_t)s1 * DIN + t), a1);
        }
        if (j < end)
            a0 = fmaf(csr_w[j], __ldg(X + (size_t)csr_src[j] * DIN + t), a0);
    }
    g0h[(size_t)node * K1 + t] = __float2half(t < DIN ? (a0 + a1) : 0.f);
}

// ---------------- layer-1 mma GEMM ------------------------------------------------
#define RS1   144
#define ARR1  (128 * RS1)
#define G1_SMEM (2 * ARR1)

__global__ void __launch_bounds__(256, 2) mma_gemm1_kernel(
    const __half* __restrict__ A0, const __half* __restrict__ B0,
    __half* __restrict__ O, int M) {
    extern __shared__ char smem[];
    uint32_t sb = smem_u32(smem);
    int tid = threadIdx.x;
    int wid = tid >> 5, lane = tid & 31;
    int wm = wid >> 2, wn = wid & 3;
    int m0 = blockIdx.y * 128;
    int n0 = blockIdx.x * 128;

    int rrow = tid >> 1;
    int half = tid & 1;
    if (m0 + 128 > M) {
        int r = tid >> 1;
        if (m0 + r >= M) {
            uint32_t a = sb + r * RS1 + half * 64;
            #pragma unroll
            for (int q = 0; q < 4; q++)
                asm volatile("st.shared.v4.b32 [%0], {%1, %1, %1, %1};"
                             :: "r"(a + q * 16), "r"(0u) : "memory");
        }
    }
    if (m0 + rrow < M) {
        const __half* gp = A0 + (size_t)(m0 + rrow) * K1 + half * 32;
        uint32_t sa = sb + rrow * RS1 + half * 64;
        #pragma unroll
        for (int q = 0; q < 4; q++) cp16(sa + q * 16, gp + q * 8);
    }
    {
        const __half* gp = B0 + (size_t)(n0 + rrow) * K1 + half * 32;
        uint32_t sa = sb + ARR1 + rrow * RS1 + half * 64;
        #pragma unroll
        for (int q = 0; q < 4; q++) cp16(sa + q * 16, gp + q * 8);
    }
    cp_commit();
    cp_wait<0>();
    __syncthreads();

    float acc[4][4][4];
    #pragma unroll
    for (int i = 0; i < 4; i++)
        #pragma unroll
        for (int j = 0; j < 4; j++)
            #pragma unroll
            for (int q = 0; q < 4; q++) acc[i][j][q] = 0.f;

    int la = lane & 15, lha = (lane >> 4) & 1;
    int lbr = (lane & 7) + ((lane >> 4) & 1) * 8;
    int lbh = (lane >> 3) & 1;

    uint32_t aB = sb + (wm * 64) * RS1;
    uint32_t bB = sb + ARR1 + (wn * 32) * RS1;

    #pragma unroll
    for (int kk = 0; kk < 4; kk++) {
        uint32_t bh[4][2];
        #pragma unroll
        for (int pair = 0; pair < 2; pair++) {
            uint32_t bd = bB + (pair * 16 + lbr) * RS1 + lbh * 16 + kk * 32;
            uint32_t r4[4];
            ldm_x4(r4, bd);
            bh[pair * 2][0] = r4[0]; bh[pair * 2][1] = r4[1];
            bh[pair * 2 + 1][0] = r4[2]; bh[pair * 2 + 1][1] = r4[3];
        }
        #pragma unroll
        for (int im = 0; im < 4; im++) {
            uint32_t ah[4];
            uint32_t ad = aB + (im * 16 + la) * RS1 + lha * 16 + kk * 32;
            ldm_x4(ah, ad);
            #pragma unroll
            for (int in = 0; in < 4; in++)
                mma16816h(acc[im][in], ah, bh[in]);
        }
    }

    int cm = m0 + wm * 64 + (lane >> 2);
    int cn0 = n0 + wn * 32 + (lane & 3) * 2;
    #pragma unroll
    for (int im = 0; im < 4; im++) {
        #pragma unroll
        for (int hf = 0; hf < 2; hf++) {
            int r = cm + im * 16 + hf * 8;
            if (r >= M) continue;
            #pragma unroll
            for (int in = 0; in < 4; in++) {
                int c = cn0 + in * 8;
                __half2 hp = __floats2half2_rn(elu_f(acc[im][in][hf * 2 + 0]),
                                               elu_f(acc[im][in][hf * 2 + 1]));
                *(__half2*)(O + (size_t)r * K2 + HID + c) = hp;
            }
        }
    }
}

// ---------------- agg: split into 2 feature-half blocks per node ------------------
__global__ void agg_half_kernel(__half* __restrict__ A,
                                const int* __restrict__ offs, const int* __restrict__ csr_src,
                                const float* __restrict__ csr_w) {
    int bx = blockIdx.x;
    int node = bx >> 1;
    int h = bx & 1;
    int tid = threadIdx.x;
    size_t cofs = HID + (size_t)h * 512 + (size_t)tid * 4;
    float a0[4] = {0.f, 0.f, 0.f, 0.f};
    float a1[4] = {0.f, 0.f, 0.f, 0.f};
    int beg = offs[node], end = offs[node + 1];
    int j = beg;
    for (; j + 1 < end; j += 2) {
        int s0 = csr_src[j], s1 = csr_src[j + 1];
        float w0 = csr_w[j], w1 = csr_w[j + 1];
        uint2 p0 = __ldg((const uint2*)(A + (size_t)s0 * K2 + cofs));
        uint2 p1 = __ldg((const uint2*)(A + (size_t)s1 * K2 + cofs));
        float2 v00 = __half22float2(*(__half2*)&p0.x);
        float2 v01 = __half22float2(*(__half2*)&p0.y);
        float2 v10 = __half22float2(*(__half2*)&p1.x);
        float2 v11 = __half22float2(*(__half2*)&p1.y);
        a0[0] = fmaf(w0, v00.x, a0[0]); a0[1] = fmaf(w0, v00.y, a0[1]);
        a0[2] = fmaf(w0, v01.x, a0[2]); a0[3] = fmaf(w0, v01.y, a0[3]);
        a1[0] = fmaf(w1, v10.x, a1[0]); a1[1] = fmaf(w1, v10.y, a1[1]);
        a1[2] = fmaf(w1, v11.x, a1[2]); a1[3] = fmaf(w1, v11.y, a1[3]);
    }
    if (j < end) {
        int s0 = csr_src[j];
        float w0 = csr_w[j];
        uint2 p0 = __ldg((const uint2*)(A + (size_t)s0 * K2 + cofs));
        float2 v00 = __half22float2(*(__half2*)&p0.x);
        float2 v01 = __half22float2(*(__half2*)&p0.y);
        a0[0] = fmaf(w0, v00.x, a0[0]); a0[1] = fmaf(w0, v00.y, a0[1]);
        a0[2] = fmaf(w0, v01.x, a0[2]); a0[3] = fmaf(w0, v01.y, a0[3]);
    }
    __half2 o01 = __floats2half2_rn(a0[0] + a1[0], a0[1] + a1[1]);
    __half2 o23 = __floats2half2_rn(a0[2] + a1[2], a0[3] + a1[3]);
    uint2 pk;
    pk.x = *(uint32_t*)&o01;
    pk.y = *(uint32_t*)&o23;
    *(uint2*)(A + (size_t)node * K2 + (size_t)h * 512 + (size_t)tid * 4) = pk;
}

// ---------------- fp16 mma.sync GEMM (K=2048, KC=32, 2 CTAs/SM) ------------------
#define KC    32
#define NCH   (K2 / KC)         // 64 chunks
#define RS    80                // 64B data + 16B pad
#define ARR_B (128 * RS)        // 10240
#define STG_B (2 * ARR_B)       // 20480
#define MMA_SMEM (2 * STG_B)    // 40960

__device__ __forceinline__ void mma_load_chunk(
    uint32_t st, int k0,
    const __half* __restrict__ A, const __half* __restrict__ B,
    int tid, int m0, int n0, int M) {
    int rrow = tid >> 1;           // 0..127
    int half = tid & 1;            // 32B half of 64B row
    {
        int grow = m0 + rrow;
        if (grow < M) {
            const __half* gp = A + (size_t)grow * K2 + k0 + half * 16;
            uint32_t sa = st + rrow * RS + half * 32;
            cp16(sa, gp);
            cp16(sa + 16, gp + 8);
        }
    }
    {
        const __half* gp = B + (size_t)(n0 + rrow) * K2 + k0 + half * 16;
        uint32_t sa = st + ARR_B + rrow * RS + half * 32;
        cp16(sa, gp);
        cp16(sa + 16, gp + 8);
    }
    cp_commit();
}

// MODE 0: full K, elu -> fp16 O. MODE 1: split-K half, fp32 partial to Pout.
template <int MODE>
__global__ void __launch_bounds__(256, 2) mma_gemm_kernel(
    const __half* __restrict__ Ain, const __half* __restrict__ Bin,
    __half* __restrict__ O, float* __restrict__ Pout, int M) {
    extern __shared__ char smem[];
    uint32_t sb = smem_u32(smem);
    int tid = threadIdx.x;
    int wid = tid >> 5, lane = tid & 31;
    int wm = wid >> 2, wn = wid & 3;
    int m0 = blockIdx.y * 128;
    int n0, kbase, nch;
    if (MODE == 0) { n0 = blockIdx.x * 128; kbase = 0;                nch = NCH;     }
    else           { n0 = 0;                kbase = blockIdx.x * HID; nch = NCH / 2; }

    if (m0 + 128 > M) {
        for (int e = tid; e < 256; e += 256) {
            int s = e >> 7, r = e & 127;
            if (m0 + r >= M) {
                uint32_t a = sb + s * STG_B + r * RS;
                #pragma unroll
                for (int q = 0; q < 4; q++)
                    asm volatile("st.shared.v4.b32 [%0], {%1, %1, %1, %1};"
                                 :: "r"(a + q * 16), "r"(0u) : "memory");
            }
        }
        __syncthreads();
    }

    float acc[4][4][4];
    #pragma unroll
    for (int i = 0; i < 4; i++)
        #pragma unroll
        for (int j = 0; j < 4; j++)
            #pragma unroll
            for (int q = 0; q < 4; q++) acc[i][j][q] = 0.f;

    mma_load_chunk(sb, kbase, Ain, Bin, tid, m0, n0, M);

    int la = lane & 15, lha = (lane >> 4) & 1;
    int lbr = (lane & 7) + ((lane >> 4) & 1) * 8;
    int lbh = (lane >> 3) & 1;

    for (int i = 0; i < nch; i++) {
        int b = i & 1;
        if (i + 1 < nch) {
            mma_load_chunk(sb + (b ^ 1) * STG_B, kbase + (i + 1) * KC, Ain, Bin,
                           tid, m0, n0, M);
            cp_wait<1>();
        } else {
            cp_wait<0>();
        }
        __syncthreads();

        uint32_t st = sb + b * STG_B;
        uint32_t aB = st + (wm * 64) * RS;
        uint32_t bB = st + ARR_B + (wn * 32) * RS;

        #pragma unroll
        for (int kk = 0; kk < 2; kk++) {
            uint32_t bh[4][2];
            #pragma unroll
            for (int pair = 0; pair < 2; pair++) {
                uint32_t bd = bB + (pair * 16 + lbr) * RS + lbh * 16 + kk * 32;
                uint32_t r4[4];
                ldm_x4(r4, bd);
                bh[pair * 2][0] = r4[0]; bh[pair * 2][1] = r4[1];
                bh[pair * 2 + 1][0] = r4[2]; bh[pair * 2 + 1][1] = r4[3];
            }
            #pragma unroll
            for (int im = 0; im < 4; im++) {
                uint32_t ah[4];
                uint32_t ad = aB + (im * 16 + la) * RS + lha * 16 + kk * 32;
                ldm_x4(ah, ad);
                #pragma unroll
                for (int in = 0; in < 4; in++)
                    mma16816h(acc[im][in], ah, bh[in]);
            }
        }
        __syncthreads();
    }

    int cm = m0 + wm * 64 + (lane >> 2);
    int cn0 = n0 + wn * 32 + (lane & 3) * 2;
    float* P = (MODE == 1) ? (Pout + (size_t)blockIdx.x * NN * NCLS) : nullptr;
    #pragma unroll
    for (int im = 0; im < 4; im++) {
        #pragma unroll
        for (int hf = 0; hf < 2; hf++) {
            int r = cm + im * 16 + hf * 8;
            if (r >= M) continue;
            #pragma unroll
            for (int in = 0; in < 4; in++) {
                int c = cn0 + in * 8;
                float v0 = acc[im][in][hf * 2 + 0];
                float v1 = acc[im][in][hf * 2 + 1];
                if (MODE == 0) {
                    __half2 hp = __floats2half2_rn(elu_f(v0), elu_f(v1));
                    *(__half2*)(O + (size_t)r * K2 + HID + c) = hp;
                } else {
                    if (c < NCLS)     P[(size_t)r * NCLS + c] = v0;
                    if (c + 1 < NCLS) P[(size_t)r * NCLS + c + 1] = v1;
                }
            }
        }
    }
}

// combine split-K partials -> d_out
__global__ void combine_kernel(const float* __restrict__ P, float* __restrict__ out) {
    int i = blockIdx.x * blockDim.x + threadIdx.x;
    if (i < NN * NCLS) out[i] = P[i] + P[(size_t)NN * NCLS + i];
}

// ---------------- launcher -------------------------------------------------------
extern "C" void kernel_launch(void* const* d_in, const int* in_sizes, int n_in,
                              void* d_out, int out_size) {
    const float* X  = (const float*)d_in[0];
    const int*   ei = (const int*)d_in[1];
    const float* W1 = (const float*)d_in[2];
    const float* W2 = (const float*)d_in[3];
    const float* S2 = (const float*)d_in[4];
    const float* W3 = (const float*)d_in[5];
    const float* S3 = (const float*)d_in[6];
    float* out = (float*)d_out;

    const int* row = ei;
    const int* col = ei + NE;

    float *w, *P;
    int *deg, *cur, *offs, *src, *bsum;
    __half *A2, *A3, *B2, *BO, *W1T, *g0h;
    cudaGetSymbolAddress((void**)&deg,  g_deg);
    cudaGetSymbolAddress((void**)&cur,  g_cursor);
    cudaGetSymbolAddress((void**)&offs, g_offs);
    cudaGetSymbolAddress((void**)&src,  g_src);
    cudaGetSymbolAddress((void**)&w,    g_w);
    cudaGetSymbolAddress((void**)&bsum, g_bsum);
    cudaGetSymbolAddress((void**)&P,    g_P);
    cudaGetSymbolAddress((void**)&A2,   g_A2);
    cudaGetSymbolAddress((void**)&A3,   g_A3);
    cudaGetSymbolAddress((void**)&B2,   g_B2);
    cudaGetSymbolAddress((void**)&BO,   g_BO);
    cudaGetSymbolAddress((void**)&W1T,  g_W1T);
    cudaGetSymbolAddress((void**)&g0h,  g_g0h);

    cudaFuncSetAttribute(mma_gemm_kernel<0>, cudaFuncAttributeMaxDynamicSharedMemorySize, MMA_SMEM);
    cudaFuncSetAttribute(mma_gemm_kernel<1>, cudaFuncAttributeMaxDynamicSharedMemorySize, MMA_SMEM);
    cudaFuncSetAttribute(mma_gemm1_kernel, cudaFuncAttributeMaxDynamicSharedMemorySize, G1_SMEM);

    static cudaStream_t s2 = nullptr;
    static cudaEvent_t evFork = nullptr, evJoin = nullptr;
    if (s2 == nullptr) {
        cudaStreamCreateWithFlags(&s2, cudaStreamNonBlocking);
        cudaEventCreateWithFlags(&evFork, cudaEventDisableTiming);
        cudaEventCreateWithFlags(&evJoin, cudaEventDisableTiming);
    }

    // ---- fork: side stream does weight prep (BO, W1T, B2) ----
    cudaEventRecord(evFork, 0);
    cudaStreamWaitEvent(s2, evFork, 0);
    prep_kernel<<<1024, 256, 0, s2>>>(W3, S3, W1, BO, W1T);
    {
        dim3 grid(32, 32, 2);
        dim3 blk(32, 8);
        transpose_w_kernel<<<grid, blk, 0, s2>>>(W2, S2, B2);
    }
    cudaEventRecord(evJoin, s2);

    // ---- main stream: CSR build + agg0 ----
    cudaMemsetAsync(deg, 0, NN * sizeof(int));
    cudaMemsetAsync(cur, 0, NN * sizeof(int));
    count_deg_kernel<<<512, 256>>>(col, deg);
    scanA_kernel<<<NN / SCAN_B, 1024>>>(deg, bsum);
    scanB_kernel<<<NN / SCAN_B, 1024>>>(deg, bsum, offs);
    fill_csr_kernel<<<512, 256>>>(row, col, offs, cur, deg, src, w);
    agg0_kernel<<<NN, 64>>>(X, g0h, offs, src, w);

    // ---- join ----
    cudaStreamWaitEvent(0, evJoin, 0);

    // h1 = elu(g0h @ W1T^T) -> A2[:,1024:]
    {
        dim3 grid(HID / 128, (NN + 127) / 128);
        mma_gemm1_kernel<<<grid, 256, G1_SMEM>>>(g0h, W1T, A2, NN);
    }
    // g1 = agg(h1) -> A2[:, 0:1024]
    agg_half_kernel<<<2 * NN, 128>>>(A2, offs, src, w);
    // h2 = elu([g1,h1] @ [W2;S2]) -> A3[:,1024:]
    {
        dim3 grid(HID / 128, (NN + 127) / 128);
        mma_gemm_kernel<0><<<grid, 256, MMA_SMEM>>>(A2, B2, A3, nullptr, NN);
    }
    // g2 = agg(h2) -> A3[:, 0:1024]
    agg_half_kernel<<<2 * NN, 128>>>(A3, offs, src, w);
    // split-K gemm3 + combine -> d_out
    {
        dim3 grid(2, (NN + 127) / 128);
        mma_gemm_kernel<1><<<grid, 256, MMA_SMEM>>>(A3, BO, nullptr, P, NN);
    }
    combine_kernel<<<(NN * NCLS + 255) / 256, 256>>>(P, out);
}